// round 1
// baseline (speedup 1.0000x reference)
#include <cuda_runtime.h>
#include <cuda_bf16.h>
#include <math.h>

// Problem constants
#define B 2
#define S 2048
#define HID 2048
#define NH 16
#define NKV 4
#define HD 128
#define CHUNK 256
#define NCH 8

// Scratch (static device allocations; no cudaMalloc allowed)
__device__ float g_Q[(size_t)B * S * NH * HD];       // [b][s][h][d]
__device__ float g_K[(size_t)B * S * NKV * HD];      // [b][s][kvh][d]
__device__ float g_V[(size_t)B * S * NKV * HD];
__device__ float g_O[(size_t)B * S * NH * HD];       // attention output [b][s][h][d]
__device__ float g_kmean[(size_t)B * NCH * NKV * HD];
__device__ unsigned g_sel[(size_t)B * NH * S];

// ---------------------------------------------------------------------------
// SGEMM: C[M,N] = A[M,K] * B[K,N], row-major, fp32. 128x128 block, BK=8,
// 256 threads, 8x8 per-thread microtile. Dims must be multiples of tile dims
// (they are: M=4096, N in {512,2048}, K=2048).
// ---------------------------------------------------------------------------
__global__ __launch_bounds__(256, 2)
void sgemm128(const float* __restrict__ A, const float* __restrict__ Bm,
              float* __restrict__ C, int M, int N, int K) {
    __shared__ float As[8][128];
    __shared__ float Bs[8][128];
    int tid = threadIdx.x;
    int bm = blockIdx.y * 128, bn = blockIdx.x * 128;
    int arow = tid >> 1, acol = (tid & 1) << 2;       // A: 128 rows x 8 cols
    int brow = tid >> 5, bcol = (tid & 31) << 2;      // B: 8 rows x 128 cols
    int tx = tid & 15, ty = tid >> 4;

    float acc[8][8];
#pragma unroll
    for (int i = 0; i < 8; i++)
#pragma unroll
        for (int j = 0; j < 8; j++) acc[i][j] = 0.f;

    for (int k0 = 0; k0 < K; k0 += 8) {
        float4 a4 = *(const float4*)(A + (size_t)(bm + arow) * K + k0 + acol);
        As[acol + 0][arow] = a4.x;
        As[acol + 1][arow] = a4.y;
        As[acol + 2][arow] = a4.z;
        As[acol + 3][arow] = a4.w;
        float4 b4 = *(const float4*)(Bm + (size_t)(k0 + brow) * N + bn + bcol);
        *(float4*)&Bs[brow][bcol] = b4;
        __syncthreads();
#pragma unroll
        for (int k = 0; k < 8; k++) {
            float ra[8], rb[8];
#pragma unroll
            for (int i = 0; i < 8; i++) ra[i] = As[k][ty * 8 + i];
#pragma unroll
            for (int j = 0; j < 8; j++) rb[j] = Bs[k][tx * 8 + j];
#pragma unroll
            for (int i = 0; i < 8; i++)
#pragma unroll
                for (int j = 0; j < 8; j++) acc[i][j] += ra[i] * rb[j];
        }
        __syncthreads();
    }
#pragma unroll
    for (int i = 0; i < 8; i++)
#pragma unroll
        for (int j = 0; j < 8; j += 4) {
            float4 v = make_float4(acc[i][j], acc[i][j + 1], acc[i][j + 2], acc[i][j + 3]);
            *(float4*)(C + (size_t)(bm + ty * 8 + i) * N + bn + tx * 8 + j) = v;
        }
}

// ---------------------------------------------------------------------------
// RoPE in place. x layout: [B*S][heads][128]. One thread per rotation pair.
// inv_freq computed in double (correctly rounded), angle as fp32 s*inv_freq
// (matches jax's fp32 multiply), sin/cos in double for accuracy.
// ---------------------------------------------------------------------------
__global__ void rope_kernel(float* __restrict__ x, int heads, int total) {
    int i = blockIdx.x * blockDim.x + threadIdx.x;
    if (i >= total) return;
    int j = i & 63;
    int rest = i >> 6;
    int h = rest % heads;
    int bs = rest / heads;
    int s = bs & (S - 1);
    double ifd = exp(-((double)(2 * j) / 128.0) * log(10000.0));
    float invf = (float)ifd;
    float ang = (float)s * invf;
    double cd, sd;
    sincos((double)ang, &sd, &cd);
    float c = (float)cd, sn = (float)sd;
    float* base = x + ((size_t)bs * heads + h) * HD;
    float x1 = base[j], x2 = base[j + 64];
    base[j]      = x1 * c - x2 * sn;
    base[j + 64] = x2 * c + x1 * sn;
}

// ---------------------------------------------------------------------------
// Per-chunk K mean (after RoPE). 64 blocks (b,n,kvh), 128 threads (d).
// ---------------------------------------------------------------------------
__global__ void kmean_kernel() {
    int id = blockIdx.x;
    int kvh = id & 3;
    int n = (id >> 2) & 7;
    int b = id >> 5;
    int d = threadIdx.x;
    const float* base = g_K + (((size_t)b * S + n * CHUNK) * NKV + kvh) * HD + d;
    float s = 0.f;
#pragma unroll 8
    for (int i = 0; i < CHUNK; i++) s += base[(size_t)i * NKV * HD];
    g_kmean[((b * NCH + n) * NKV + kvh) * HD + d] = s * (1.0f / CHUNK);
}

// ---------------------------------------------------------------------------
// Gate + top-k chunk selection. One warp per query (b,h,s). Selection:
// current chunk always (reference sets it to +inf), plus top-3 of the
// strictly-past chunks; ties -> lowest index (matches jax.lax.top_k).
// Future / -inf chunks contribute nothing (killed by causal mask) so they
// need not be recorded.
// ---------------------------------------------------------------------------
__global__ void select_kernel() {
    int w = blockIdx.x * (blockDim.x >> 5) + (threadIdx.x >> 5);
    int lane = threadIdx.x & 31;
    int s = w & (S - 1);
    int h = (w >> 11) & (NH - 1);
    int b = w >> 15;
    int kvh = h >> 2;
    int qc = s >> 8;

    const float* q = g_Q + (((size_t)b * S + s) * NH + h) * HD;
    float4 qv = *(const float4*)(q + lane * 4);
    float g[8];
    for (int n = 0; n < qc; n++) {
        const float* km = g_kmean + ((b * NCH + n) * NKV + kvh) * HD;
        float4 kv = *(const float4*)(km + lane * 4);
        float p = qv.x * kv.x + qv.y * kv.y + qv.z * kv.z + qv.w * kv.w;
#pragma unroll
        for (int o = 16; o; o >>= 1) p += __shfl_xor_sync(0xffffffffu, p, o);
        g[n] = p;
    }
    if (lane == 0) {
        unsigned sel = 1u << qc;
        for (int it = 0; it < 3; it++) {
            float best = 0.f;
            int bi = -1;
            for (int n = 0; n < qc; n++)
                if (!((sel >> n) & 1) && (bi < 0 || g[n] > best)) { best = g[n]; bi = n; }
            if (bi >= 0) sel |= 1u << bi;
        }
        g_sel[w] = sel;
    }
}

// ---------------------------------------------------------------------------
// Sparse attention. One block (128 threads) per query (s, h, b).
// Enumerates only valid keys (selected past chunks fully, current chunk up
// to s), so no masking/-inf handling is needed in the softmax.
// ---------------------------------------------------------------------------
__global__ __launch_bounds__(128)
void attn_kernel() {
    __shared__ float qs[128];
    __shared__ float sc[1024];
    __shared__ float red[128];
    __shared__ int cl[4];
    __shared__ int s_ntot;

    int s = blockIdx.x, h = blockIdx.y, b = blockIdx.z;
    int tid = threadIdx.x;
    int kvh = h >> 2;

    qs[tid] = g_Q[(((size_t)b * S + s) * NH + h) * HD + tid];
    if (tid == 0) {
        unsigned sel = g_sel[(((size_t)b * NH + h) << 11) + s];
        int qc = s >> 8;
        int nc = 0;
        for (int n = 0; n < qc; n++)
            if ((sel >> n) & 1) cl[nc++] = n;
        cl[nc++] = qc;                         // current chunk last (partial)
        s_ntot = ((nc - 1) << 8) + (s & 255) + 1;
    }
    __syncthreads();
    int ntot = s_ntot;
    int warp = tid >> 5, lane = tid & 31;
    const float scale = 0.08838834764831845f;  // 1/sqrt(128)

    // scores
    for (int kk = warp; kk < ntot; kk += 4) {
        int t = (cl[kk >> 8] << 8) + (kk & 255);
        const float* kr = g_K + (((size_t)b * S + t) * NKV + kvh) * HD + lane * 4;
        float4 kv = *(const float4*)kr;
        float4 qv = *(const float4*)&qs[lane * 4];
        float p = qv.x * kv.x + qv.y * kv.y + qv.z * kv.z + qv.w * kv.w;
#pragma unroll
        for (int o = 16; o; o >>= 1) p += __shfl_xor_sync(0xffffffffu, p, o);
        if (lane == 0) sc[kk] = p * scale;
    }
    __syncthreads();

    // max
    float mx = -1e30f;
    for (int kk = tid; kk < ntot; kk += 128) mx = fmaxf(mx, sc[kk]);
    red[tid] = mx;
    __syncthreads();
    for (int st = 64; st; st >>= 1) {
        if (tid < st) red[tid] = fmaxf(red[tid], red[tid + st]);
        __syncthreads();
    }
    mx = red[0];
    __syncthreads();

    // exp + sum
    float sm = 0.f;
    for (int kk = tid; kk < ntot; kk += 128) {
        float e = expf(sc[kk] - mx);
        sc[kk] = e;
        sm += e;
    }
    red[tid] = sm;
    __syncthreads();
    for (int st = 64; st; st >>= 1) {
        if (tid < st) red[tid] += red[tid + st];
        __syncthreads();
    }
    float inv = 1.0f / red[0];
    __syncthreads();

    // output: thread = dim d, loop keys (unroll x4 for MLP)
    float a0 = 0.f, a1 = 0.f, a2 = 0.f, a3 = 0.f;
    const float* vb = g_V + ((size_t)b * S * NKV + kvh) * HD + tid;
    int kk = 0;
    for (; kk + 4 <= ntot; kk += 4) {
        int t0 = (cl[(kk + 0) >> 8] << 8) + ((kk + 0) & 255);
        int t1 = (cl[(kk + 1) >> 8] << 8) + ((kk + 1) & 255);
        int t2 = (cl[(kk + 2) >> 8] << 8) + ((kk + 2) & 255);
        int t3 = (cl[(kk + 3) >> 8] << 8) + ((kk + 3) & 255);
        a0 += sc[kk + 0] * vb[(size_t)t0 * NKV * HD];
        a1 += sc[kk + 1] * vb[(size_t)t1 * NKV * HD];
        a2 += sc[kk + 2] * vb[(size_t)t2 * NKV * HD];
        a3 += sc[kk + 3] * vb[(size_t)t3 * NKV * HD];
    }
    for (; kk < ntot; kk++) {
        int t = (cl[kk >> 8] << 8) + (kk & 255);
        a0 += sc[kk] * vb[(size_t)t * NKV * HD];
    }
    g_O[(((size_t)b * S + s) * NH + h) * HD + tid] = (a0 + a1 + a2 + a3) * inv;
}

// ---------------------------------------------------------------------------
extern "C" void kernel_launch(void* const* d_in, const int* in_sizes, int n_in,
                              void* d_out, int out_size) {
    const float* x  = (const float*)d_in[0];
    const float* wq = (const float*)d_in[1];
    const float* wk = (const float*)d_in[2];
    const float* wv = (const float*)d_in[3];
    const float* wo = (const float*)d_in[4];
    float* out = (float*)d_out;

    float *Q, *K, *V, *O;
    cudaGetSymbolAddress((void**)&Q, g_Q);
    cudaGetSymbolAddress((void**)&K, g_K);
    cudaGetSymbolAddress((void**)&V, g_V);
    cudaGetSymbolAddress((void**)&O, g_O);

    const int M = B * S;  // 4096

    // projections
    sgemm128<<<dim3((NH * HD) / 128, M / 128), 256>>>(x, wq, Q, M, NH * HD, HID);
    sgemm128<<<dim3((NKV * HD) / 128, M / 128), 256>>>(x, wk, K, M, NKV * HD, HID);
    sgemm128<<<dim3((NKV * HD) / 128, M / 128), 256>>>(x, wv, V, M, NKV * HD, HID);

    // RoPE
    {
        int totq = B * S * NH * 64;
        rope_kernel<<<(totq + 255) / 256, 256>>>(Q, NH, totq);
        int totk = B * S * NKV * 64;
        rope_kernel<<<(totk + 255) / 256, 256>>>(K, NKV, totk);
    }

    // chunk means + gate/top-k selection
    kmean_kernel<<<B * NCH * NKV, 128>>>();
    select_kernel<<<(B * NH * S) / 8, 256>>>();

    // sparse attention
    attn_kernel<<<dim3(S, NH, B), 128>>>();

    // output projection
    sgemm128<<<dim3(HID / 128, M / 128), 256>>>(O, wo, out, M, HID, HID);
}

// round 2
// speedup vs baseline: 1.4845x; 1.4845x over previous
#include <cuda_runtime.h>
#include <cuda_bf16.h>
#include <math.h>

// Problem constants
#define B 2
#define S 2048
#define HID 2048
#define NH 16
#define NKV 4
#define HD 128
#define CHUNK 256
#define NCH 8

// Attention tiling
#define QT 64
#define KT 32

// Scratch (static device allocations; no cudaMalloc allowed)
__device__ float g_Q[(size_t)B * S * NH * HD];       // [b][s][h][d]
__device__ float g_K[(size_t)B * S * NKV * HD];      // [b][s][kvh][d]
__device__ float g_V[(size_t)B * S * NKV * HD];
__device__ float g_O[(size_t)B * S * NH * HD];       // attention output [b][s][h][d]
__device__ float g_kmean[(size_t)B * NCH * NKV * HD];
__device__ unsigned g_sel[(size_t)B * NH * S];
__device__ float g_rc[(size_t)S * 64];               // rope cos table [s][j]
__device__ float g_rs[(size_t)S * 64];               // rope sin table [s][j]

// ---------------------------------------------------------------------------
// SGEMM: C[M,N] = A[M,K] * B[K,N], row-major, fp32. 128x128 block, BK=8,
// 256 threads, 8x8 per-thread microtile.
// ---------------------------------------------------------------------------
__global__ __launch_bounds__(256, 2)
void sgemm128(const float* __restrict__ A, const float* __restrict__ Bm,
              float* __restrict__ C, int M, int N, int K) {
    __shared__ float As[8][128];
    __shared__ float Bs[8][128];
    int tid = threadIdx.x;
    int bm = blockIdx.y * 128, bn = blockIdx.x * 128;
    int arow = tid >> 1, acol = (tid & 1) << 2;
    int brow = tid >> 5, bcol = (tid & 31) << 2;
    int tx = tid & 15, ty = tid >> 4;

    float acc[8][8];
#pragma unroll
    for (int i = 0; i < 8; i++)
#pragma unroll
        for (int j = 0; j < 8; j++) acc[i][j] = 0.f;

    for (int k0 = 0; k0 < K; k0 += 8) {
        float4 a4 = *(const float4*)(A + (size_t)(bm + arow) * K + k0 + acol);
        As[acol + 0][arow] = a4.x;
        As[acol + 1][arow] = a4.y;
        As[acol + 2][arow] = a4.z;
        As[acol + 3][arow] = a4.w;
        float4 b4 = *(const float4*)(Bm + (size_t)(k0 + brow) * N + bn + bcol);
        *(float4*)&Bs[brow][bcol] = b4;
        __syncthreads();
#pragma unroll
        for (int k = 0; k < 8; k++) {
            float ra[8], rb[8];
#pragma unroll
            for (int i = 0; i < 8; i++) ra[i] = As[k][ty * 8 + i];
#pragma unroll
            for (int j = 0; j < 8; j++) rb[j] = Bs[k][tx * 8 + j];
#pragma unroll
            for (int i = 0; i < 8; i++)
#pragma unroll
                for (int j = 0; j < 8; j++) acc[i][j] += ra[i] * rb[j];
        }
        __syncthreads();
    }
#pragma unroll
    for (int i = 0; i < 8; i++)
#pragma unroll
        for (int j = 0; j < 8; j += 4) {
            float4 v = make_float4(acc[i][j], acc[i][j + 1], acc[i][j + 2], acc[i][j + 3]);
            *(float4*)(C + (size_t)(bm + ty * 8 + i) * N + bn + tx * 8 + j) = v;
        }
}

// ---------------------------------------------------------------------------
// RoPE table: cos/sin for (s, j). inv_freq in double (correctly rounded to
// fp32), angle as fp32 s*invf (matches jax fp32 multiply), sincos in double.
// Only S*64 = 131072 threads do FP64 work (vs 5.2M before).
// ---------------------------------------------------------------------------
__global__ void rope_table_kernel() {
    int i = blockIdx.x * blockDim.x + threadIdx.x;
    if (i >= S * 64) return;
    int j = i & 63;
    int s = i >> 6;
    double ifd = exp(-((double)(2 * j) / 128.0) * log(10000.0));
    float invf = (float)ifd;
    float ang = (float)s * invf;
    double cd, sd;
    sincos((double)ang, &sd, &cd);
    g_rc[i] = (float)cd;
    g_rs[i] = (float)sd;
}

// RoPE apply from table. x layout: [B*S][heads][128].
__global__ void rope_apply_kernel(float* __restrict__ x, int heads, int total) {
    int i = blockIdx.x * blockDim.x + threadIdx.x;
    if (i >= total) return;
    int j = i & 63;
    int rest = i >> 6;
    int h = rest % heads;
    int bs = rest / heads;
    int s = bs & (S - 1);
    float c = g_rc[s * 64 + j];
    float sn = g_rs[s * 64 + j];
    float* base = x + ((size_t)bs * heads + h) * HD;
    float x1 = base[j], x2 = base[j + 64];
    base[j]      = x1 * c - x2 * sn;
    base[j + 64] = x2 * c + x1 * sn;
}

// ---------------------------------------------------------------------------
// Per-chunk K mean (after RoPE). 64 blocks (b,n,kvh), 128 threads (d).
// ---------------------------------------------------------------------------
__global__ void kmean_kernel() {
    int id = blockIdx.x;
    int kvh = id & 3;
    int n = (id >> 2) & 7;
    int b = id >> 5;
    int d = threadIdx.x;
    const float* base = g_K + (((size_t)b * S + n * CHUNK) * NKV + kvh) * HD + d;
    float s = 0.f;
#pragma unroll 8
    for (int i = 0; i < CHUNK; i++) s += base[(size_t)i * NKV * HD];
    g_kmean[((b * NCH + n) * NKV + kvh) * HD + d] = s * (1.0f / CHUNK);
}

// ---------------------------------------------------------------------------
// Gate + top-k chunk selection. One warp per query.
// ---------------------------------------------------------------------------
__global__ void select_kernel() {
    int w = blockIdx.x * (blockDim.x >> 5) + (threadIdx.x >> 5);
    int lane = threadIdx.x & 31;
    int s = w & (S - 1);
    int h = (w >> 11) & (NH - 1);
    int b = w >> 15;
    int kvh = h >> 2;
    int qc = s >> 8;

    const float* q = g_Q + (((size_t)b * S + s) * NH + h) * HD;
    float4 qv = *(const float4*)(q + lane * 4);
    float g[8];
    for (int n = 0; n < qc; n++) {
        const float* km = g_kmean + ((b * NCH + n) * NKV + kvh) * HD;
        float4 kv = *(const float4*)(km + lane * 4);
        float p = qv.x * kv.x + qv.y * kv.y + qv.z * kv.z + qv.w * kv.w;
#pragma unroll
        for (int o = 16; o; o >>= 1) p += __shfl_xor_sync(0xffffffffu, p, o);
        g[n] = p;
    }
    if (lane == 0) {
        unsigned sel = 1u << qc;
        for (int it = 0; it < 3; it++) {
            float best = 0.f;
            int bi = -1;
            for (int n = 0; n < qc; n++)
                if (!((sel >> n) & 1) && (bi < 0 || g[n] > best)) { best = g[n]; bi = n; }
            if (bi >= 0) sel |= 1u << bi;
        }
        g_sel[w] = sel;
    }
}

// ---------------------------------------------------------------------------
// Tiled sparse flash attention. Block = 256 threads, QT=64 queries (one
// (b,h) head, one query tile), keys processed in KT=32 tiles staged in smem.
// Chunk-level sel-union skip + per-query chunk mask + causal in own chunk.
// Online softmax; PV accumulators in registers (4q x 8d per thread).
//
// smem strides chosen for bank-conflict-free hot loops:
//   Qs stride 132 (float4-aligned, broadcast-safe), Ks stride 129
//   (scalar-staged, conflict-free QK rb), Vs 128, Ps 68 (float4-aligned).
// ---------------------------------------------------------------------------
#define QS_STRIDE 132
#define KS_STRIDE 129
#define PS_STRIDE 68
#define ATTN_SMEM_FLOATS (QT * QS_STRIDE + KT * KS_STRIDE + KT * HD + KT * PS_STRIDE + 3 * QT + QT + 8)

__global__ __launch_bounds__(256)
void attn_tile_kernel() {
    extern __shared__ float sm[];
    float* Qs = sm;                              // [QT][132]
    float* Ks = Qs + QT * QS_STRIDE;             // [KT][129]
    float* Vs = Ks + KT * KS_STRIDE;             // [KT][128]
    float* Ps = Vs + KT * HD;                    // [KT][68]
    float* m_s = Ps + KT * PS_STRIDE;            // [QT]
    float* l_s = m_s + QT;
    float* scl = l_s + QT;
    unsigned* selq = (unsigned*)(scl + QT);      // [QT]
    unsigned* selu_p = selq + QT;

    // Long tiles first (work ~ qt) to reduce wave tail.
    int qt = gridDim.x - 1 - blockIdx.x;
    int h = blockIdx.y, b = blockIdx.z;
    int tid = threadIdx.x;
    int kvh = h >> 2;
    int s0 = qt * QT;
    int qc = s0 >> 8;

    // ---- stage Q tile + per-query state ----
    {
        int q = tid >> 2, part = tid & 3;
        const float* qr = g_Q + (((size_t)b * S + s0 + q) * NH + h) * HD + part * 32;
#pragma unroll
        for (int i = 0; i < 8; i++)
            *(float4*)&Qs[q * QS_STRIDE + part * 32 + i * 4] = *(const float4*)(qr + i * 4);
    }
    if (tid == 0) *selu_p = 0;
    __syncthreads();
    if (tid < QT) {
        unsigned sv = g_sel[(((size_t)b * NH + h) << 11) + s0 + tid];
        selq[tid] = sv;
        atomicOr(selu_p, sv);
        m_s[tid] = -1e30f;
        l_s[tid] = 0.f;
    }
    __syncthreads();
    unsigned selu = *selu_p;

    float acc[4][8];
#pragma unroll
    for (int i = 0; i < 4; i++)
#pragma unroll
        for (int j = 0; j < 8; j++) acc[i][j] = 0.f;

    const float scale = 0.08838834764831845f;  // 1/sqrt(128)
    int nkt = (s0 >> 5) + 2;

    int qb = (tid >> 4) * 4;        // QK: 4 queries
    int kb = (tid & 15) * 2;        // QK: 2 keys
    int qg = tid >> 4;              // PV: 4 queries (qg*4)
    int dg = tid & 15;              // PV: 8 dims (dg*8)

    for (int kt = 0; kt < nkt; kt++) {
        int n = kt >> 3;
        if (n < qc && !((selu >> n) & 1)) continue;

        // ---- stage K (scalar, stride 129) and V (float4, stride 128) ----
        {
            int k = tid >> 3, part = tid & 7;
            size_t row = (((size_t)b * S + kt * KT + k) * NKV + kvh) * (size_t)HD;
            const float* kr = g_K + row + part * 16;
            const float* vr = g_V + row + part * 16;
#pragma unroll
            for (int i = 0; i < 4; i++) {
                float4 a = *(const float4*)(kr + i * 4);
                Ks[k * KS_STRIDE + part * 16 + i * 4 + 0] = a.x;
                Ks[k * KS_STRIDE + part * 16 + i * 4 + 1] = a.y;
                Ks[k * KS_STRIDE + part * 16 + i * 4 + 2] = a.z;
                Ks[k * KS_STRIDE + part * 16 + i * 4 + 3] = a.w;
                *(float4*)&Vs[k * HD + part * 16 + i * 4] = *(const float4*)(vr + i * 4);
            }
        }
        __syncthreads();

        // ---- QK: c[4q][2k] over d=128 ----
        float c00 = 0.f, c01 = 0.f, c10 = 0.f, c11 = 0.f;
        float c20 = 0.f, c21 = 0.f, c30 = 0.f, c31 = 0.f;
#pragma unroll 4
        for (int d = 0; d < HD; d++) {
            float b0 = Ks[(kb + 0) * KS_STRIDE + d];
            float b1 = Ks[(kb + 1) * KS_STRIDE + d];
            float r0 = Qs[(qb + 0) * QS_STRIDE + d];
            float r1 = Qs[(qb + 1) * QS_STRIDE + d];
            float r2 = Qs[(qb + 2) * QS_STRIDE + d];
            float r3 = Qs[(qb + 3) * QS_STRIDE + d];
            c00 += r0 * b0; c01 += r0 * b1;
            c10 += r1 * b0; c11 += r1 * b1;
            c20 += r2 * b0; c21 += r2 * b1;
            c30 += r3 * b0; c31 += r3 * b1;
        }
        // ---- mask + store scores transposed Ps[k][q] ----
        {
            float cs[4][2] = {{c00, c01}, {c10, c11}, {c20, c21}, {c30, c31}};
#pragma unroll
            for (int i = 0; i < 4; i++) {
#pragma unroll
                for (int j = 0; j < 2; j++) {
                    int q = qb + i, k = kb + j;
                    int tg = kt * KT + k;
                    float v = cs[i][j] * scale;
                    bool ok = (n < qc) ? ((selq[q] >> n) & 1) : (tg <= s0 + q);
                    Ps[k * PS_STRIDE + q] = ok ? v : -3.0e38f;
                }
            }
        }
        __syncthreads();

        // ---- online softmax update (64 threads, one per query) ----
        if (tid < QT) {
            float mo = m_s[tid];
            float mx = mo;
#pragma unroll 8
            for (int k = 0; k < KT; k++) mx = fmaxf(mx, Ps[k * PS_STRIDE + tid]);
            float mul = __expf(mo - mx);
            float sum = 0.f;
#pragma unroll 8
            for (int k = 0; k < KT; k++) {
                float p = __expf(Ps[k * PS_STRIDE + tid] - mx);
                Ps[k * PS_STRIDE + tid] = p;
                sum += p;
            }
            l_s[tid] = l_s[tid] * mul + sum;
            m_s[tid] = mx;
            scl[tid] = mul;
        }
        __syncthreads();

        // ---- PV: acc[4q][8d] += P[k][q] * V[k][d], with rescale ----
        {
            float f0 = scl[qg * 4 + 0], f1 = scl[qg * 4 + 1];
            float f2 = scl[qg * 4 + 2], f3 = scl[qg * 4 + 3];
#pragma unroll
            for (int j = 0; j < 8; j++) {
                acc[0][j] *= f0; acc[1][j] *= f1;
                acc[2][j] *= f2; acc[3][j] *= f3;
            }
#pragma unroll 2
            for (int k = 0; k < KT; k++) {
                float4 p4 = *(float4*)&Ps[k * PS_STRIDE + qg * 4];
                float4 v0 = *(float4*)&Vs[k * HD + dg * 8];
                float4 v1 = *(float4*)&Vs[k * HD + dg * 8 + 4];
                acc[0][0] += p4.x * v0.x; acc[0][1] += p4.x * v0.y;
                acc[0][2] += p4.x * v0.z; acc[0][3] += p4.x * v0.w;
                acc[0][4] += p4.x * v1.x; acc[0][5] += p4.x * v1.y;
                acc[0][6] += p4.x * v1.z; acc[0][7] += p4.x * v1.w;
                acc[1][0] += p4.y * v0.x; acc[1][1] += p4.y * v0.y;
                acc[1][2] += p4.y * v0.z; acc[1][3] += p4.y * v0.w;
                acc[1][4] += p4.y * v1.x; acc[1][5] += p4.y * v1.y;
                acc[1][6] += p4.y * v1.z; acc[1][7] += p4.y * v1.w;
                acc[2][0] += p4.z * v0.x; acc[2][1] += p4.z * v0.y;
                acc[2][2] += p4.z * v0.z; acc[2][3] += p4.z * v0.w;
                acc[2][4] += p4.z * v1.x; acc[2][5] += p4.z * v1.y;
                acc[2][6] += p4.z * v1.z; acc[2][7] += p4.z * v1.w;
                acc[3][0] += p4.w * v0.x; acc[3][1] += p4.w * v0.y;
                acc[3][2] += p4.w * v0.z; acc[3][3] += p4.w * v0.w;
                acc[3][4] += p4.w * v1.x; acc[3][5] += p4.w * v1.y;
                acc[3][6] += p4.w * v1.z; acc[3][7] += p4.w * v1.w;
            }
        }
        __syncthreads();   // before next tile overwrites Ks/Vs/Ps
    }

    // ---- epilogue: normalize + store ----
#pragma unroll
    for (int i = 0; i < 4; i++) {
        int q = qg * 4 + i;
        float inv = 1.0f / l_s[q];
        float* o = g_O + (((size_t)b * S + s0 + q) * NH + h) * HD + dg * 8;
        float4 w0 = make_float4(acc[i][0] * inv, acc[i][1] * inv, acc[i][2] * inv, acc[i][3] * inv);
        float4 w1 = make_float4(acc[i][4] * inv, acc[i][5] * inv, acc[i][6] * inv, acc[i][7] * inv);
        *(float4*)o = w0;
        *(float4*)(o + 4) = w1;
    }
}

// ---------------------------------------------------------------------------
extern "C" void kernel_launch(void* const* d_in, const int* in_sizes, int n_in,
                              void* d_out, int out_size) {
    const float* x  = (const float*)d_in[0];
    const float* wq = (const float*)d_in[1];
    const float* wk = (const float*)d_in[2];
    const float* wv = (const float*)d_in[3];
    const float* wo = (const float*)d_in[4];
    float* out = (float*)d_out;

    float *Q, *K, *V, *O;
    cudaGetSymbolAddress((void**)&Q, g_Q);
    cudaGetSymbolAddress((void**)&K, g_K);
    cudaGetSymbolAddress((void**)&V, g_V);
    cudaGetSymbolAddress((void**)&O, g_O);

    const int M = B * S;  // 4096
    const int attn_smem = ATTN_SMEM_FLOATS * 4;
    cudaFuncSetAttribute(attn_tile_kernel,
                         cudaFuncAttributeMaxDynamicSharedMemorySize, attn_smem);

    // rope table (cheap; also overlaps nothing of value)
    rope_table_kernel<<<(S * 64 + 255) / 256, 256>>>();

    // projections
    sgemm128<<<dim3((NH * HD) / 128, M / 128), 256>>>(x, wq, Q, M, NH * HD, HID);
    sgemm128<<<dim3((NKV * HD) / 128, M / 128), 256>>>(x, wk, K, M, NKV * HD, HID);
    sgemm128<<<dim3((NKV * HD) / 128, M / 128), 256>>>(x, wv, V, M, NKV * HD, HID);

    // RoPE apply
    {
        int totq = B * S * NH * 64;
        rope_apply_kernel<<<(totq + 255) / 256, 256>>>(Q, NH, totq);
        int totk = B * S * NKV * 64;
        rope_apply_kernel<<<(totk + 255) / 256, 256>>>(K, NKV, totk);
    }

    // chunk means + gate/top-k selection
    kmean_kernel<<<B * NCH * NKV, 128>>>();
    select_kernel<<<(B * NH * S) / 8, 256>>>();

    // tiled sparse attention
    attn_tile_kernel<<<dim3(S / QT, NH, B), 256, attn_smem>>>();

    // output projection
    sgemm128<<<dim3(HID / 128, M / 128), 256>>>(O, wo, out, M, HID, HID);
}

// round 4
// speedup vs baseline: 2.2096x; 1.4884x over previous
#include <cuda_runtime.h>
#include <cuda_bf16.h>
#include <math.h>
#include <stdint.h>

// Problem constants
#define B 2
#define S 2048
#define HID 2048
#define NH 16
#define NKV 4
#define HD 128
#define CHUNK 256
#define NCH 8

// Attention tiling
#define QT 64
#define KT 32

// Scratch (static device allocations; no cudaMalloc allowed)
__device__ float g_Q[(size_t)B * S * NH * HD];
__device__ float g_K[(size_t)B * S * NKV * HD];
__device__ float g_V[(size_t)B * S * NKV * HD];
__device__ float g_O[(size_t)B * S * NH * HD];
__device__ float g_kmean[(size_t)B * NCH * NKV * HD];
__device__ unsigned g_sel[(size_t)B * NH * S];
__device__ float g_rc[(size_t)S * 64];
__device__ float g_rs[(size_t)S * 64];

// bf16 hi/lo split copies (pre-split once; GEMMs read these)
__device__ __nv_bfloat16 g_xh[(size_t)B * S * HID];
__device__ __nv_bfloat16 g_xl[(size_t)B * S * HID];
__device__ __nv_bfloat16 g_wqh[(size_t)HID * NH * HD];
__device__ __nv_bfloat16 g_wql[(size_t)HID * NH * HD];
__device__ __nv_bfloat16 g_wkh[(size_t)HID * NKV * HD];
__device__ __nv_bfloat16 g_wkl[(size_t)HID * NKV * HD];
__device__ __nv_bfloat16 g_wvh[(size_t)HID * NKV * HD];
__device__ __nv_bfloat16 g_wvl[(size_t)HID * NKV * HD];
__device__ __nv_bfloat16 g_woh[(size_t)NH * HD * HID];
__device__ __nv_bfloat16 g_wol[(size_t)NH * HD * HID];
__device__ __nv_bfloat16 g_oh[(size_t)B * S * NH * HD];
__device__ __nv_bfloat16 g_ol[(size_t)B * S * NH * HD];

// ===========================================================================
// helpers
// ===========================================================================
__device__ __forceinline__ uint32_t smem_u32(const void* p) {
    uint32_t a;
    asm("{ .reg .u64 t; cvta.to.shared.u64 t, %1; cvt.u32.u64 %0, t; }"
        : "=r"(a) : "l"(p));
    return a;
}

__device__ __forceinline__ void ldsm4(uint32_t* r, uint32_t addr) {
    asm volatile("ldmatrix.sync.aligned.m8n8.x4.shared.b16 {%0,%1,%2,%3}, [%4];"
                 : "=r"(r[0]), "=r"(r[1]), "=r"(r[2]), "=r"(r[3]) : "r"(addr));
}
__device__ __forceinline__ void ldsm4t(uint32_t* r, uint32_t addr) {
    asm volatile("ldmatrix.sync.aligned.m8n8.x4.trans.shared.b16 {%0,%1,%2,%3}, [%4];"
                 : "=r"(r[0]), "=r"(r[1]), "=r"(r[2]), "=r"(r[3]) : "r"(addr));
}
__device__ __forceinline__ void mma16816(float* c, const uint32_t* a,
                                         uint32_t b0, uint32_t b1) {
    asm volatile(
        "mma.sync.aligned.m16n8k16.row.col.f32.bf16.bf16.f32 "
        "{%0,%1,%2,%3}, {%4,%5,%6,%7}, {%8,%9}, {%0,%1,%2,%3};"
        : "+f"(c[0]), "+f"(c[1]), "+f"(c[2]), "+f"(c[3])
        : "r"(a[0]), "r"(a[1]), "r"(a[2]), "r"(a[3]), "r"(b0), "r"(b1));
}

// exact fp32 -> (bf16 hi, bf16 lo)
__device__ __forceinline__ void split1(float a, __nv_bfloat16& h, __nv_bfloat16& l) {
    h = __float2bfloat16_rn(a);
    l = __float2bfloat16_rn(a - __bfloat162float(h));
}

// ---------------------------------------------------------------------------
// split kernel: fp32 -> bf16 hi + lo (float4 granular)
// ---------------------------------------------------------------------------
__global__ void split_kernel(const float* __restrict__ in,
                             __nv_bfloat16* __restrict__ hi,
                             __nv_bfloat16* __restrict__ lo, int n4) {
    int i = blockIdx.x * blockDim.x + threadIdx.x;
    if (i >= n4) return;
    float4 v = ((const float4*)in)[i];
    __nv_bfloat16 h0, h1, h2, h3, l0, l1, l2, l3;
    split1(v.x, h0, l0);
    split1(v.y, h1, l1);
    split1(v.z, h2, l2);
    split1(v.w, h3, l3);
    uint32_t ha = ((uint32_t)__bfloat16_as_ushort(h1) << 16) | __bfloat16_as_ushort(h0);
    uint32_t hb = ((uint32_t)__bfloat16_as_ushort(h3) << 16) | __bfloat16_as_ushort(h2);
    uint32_t la = ((uint32_t)__bfloat16_as_ushort(l1) << 16) | __bfloat16_as_ushort(l0);
    uint32_t lb = ((uint32_t)__bfloat16_as_ushort(l3) << 16) | __bfloat16_as_ushort(l2);
    ((uint2*)hi)[i] = make_uint2(ha, hb);
    ((uint2*)lo)[i] = make_uint2(la, lb);
}

// ===========================================================================
// bf16x3 GEMM via mma.sync (m16n8k16): C[M,N] = A[M,K] * W[K,N], fp32 out.
// A pre-split K-contiguous [M][K]; W pre-split row-major [K][N].
// Block 128x128xBK32, 256 threads, 8 warps (4 M x 2 N), warp tile 32x64.
// ===========================================================================
#define GBM 128
#define GBN 128
#define GBK 32

__global__ __launch_bounds__(256)
void gemm_mma(const __nv_bfloat16* __restrict__ Ah, const __nv_bfloat16* __restrict__ Al,
              const __nv_bfloat16* __restrict__ Bh, const __nv_bfloat16* __restrict__ Bl,
              float* __restrict__ C, int M, int N, int K) {
    __shared__ __align__(16) __nv_bfloat16 Ash[128][40];   // stride 80B (16-mult)
    __shared__ __align__(16) __nv_bfloat16 Asl[128][40];
    __shared__ __align__(16) __nv_bfloat16 Bsh[32][136];   // stride 272B (16-mult)
    __shared__ __align__(16) __nv_bfloat16 Bsl[32][136];

    int tid = threadIdx.x;
    int lane = tid & 31, wid = tid >> 5;
    int wm = wid & 3, wn = wid >> 2;          // warp tile: rows wm*32, cols wn*64
    int bm = blockIdx.y * GBM, bn = blockIdx.x * GBN;

    float acc[2][8][4];
#pragma unroll
    for (int i = 0; i < 2; i++)
#pragma unroll
        for (int j = 0; j < 8; j++)
#pragma unroll
            for (int k = 0; k < 4; k++) acc[i][j][k] = 0.f;

    uint32_t ash = smem_u32(Ash), asl = smem_u32(Asl);
    uint32_t bsh = smem_u32(Bsh), bsl = smem_u32(Bsl);

    // ldmatrix lane addressing
    int l15 = lane & 15, l16 = lane >> 4;
    // A: row = wm*32 + ma*16 + l15 ; byte = row*80 + ka*32 + l16*16
    uint32_t a_off = (uint32_t)(wm * 32 + l15) * 80 + l16 * 16;
    // B: row = ka*16 + ((lane>>3)&1)*8 + (lane&7) ; byte = row*272 + wn*128 + nt*32 + l16*16
    uint32_t b_off = (uint32_t)(((lane >> 3) & 1) * 8 + (lane & 7)) * 272
                   + wn * 128 + l16 * 16;

    for (int k0 = 0; k0 < K; k0 += GBK) {
        // ---- stage tiles (bf16, vector copies) ----
#pragma unroll
        for (int i = 0; i < 4; i++) {
            int s = tid + i * 256;
            int row = s >> 3, q = s & 7;
            size_t g = (size_t)(bm + row) * K + k0 + q * 4;
            *(uint2*)&Ash[row][q * 4] = *(const uint2*)(Ah + g);
            *(uint2*)&Asl[row][q * 4] = *(const uint2*)(Al + g);
        }
#pragma unroll
        for (int i = 0; i < 2; i++) {
            int s = tid + i * 256;
            int row = s >> 4, q = s & 15;
            size_t g = (size_t)(k0 + row) * N + bn + q * 8;
            *(uint4*)&Bsh[row][q * 8] = *(const uint4*)(Bh + g);
            *(uint4*)&Bsl[row][q * 8] = *(const uint4*)(Bl + g);
        }
        __syncthreads();

#pragma unroll
        for (int ka = 0; ka < 2; ka++) {
            uint32_t ahf[2][4], alf[2][4];
            ldsm4(ahf[0], ash + a_off + ka * 32);
            ldsm4(ahf[1], ash + a_off + ka * 32 + 16 * 80);
            ldsm4(alf[0], asl + a_off + ka * 32);
            ldsm4(alf[1], asl + a_off + ka * 32 + 16 * 80);
#pragma unroll
            for (int nt = 0; nt < 4; nt++) {
                uint32_t bhf[4], blf[4];
                uint32_t bo = b_off + ka * 16 * 272 + nt * 32;
                ldsm4t(bhf, bsh + bo);
                ldsm4t(blf, bsl + bo);
#pragma unroll
                for (int ma = 0; ma < 2; ma++) {
                    mma16816(acc[ma][nt * 2],     ahf[ma], bhf[0], bhf[1]);
                    mma16816(acc[ma][nt * 2],     ahf[ma], blf[0], blf[1]);
                    mma16816(acc[ma][nt * 2],     alf[ma], bhf[0], bhf[1]);
                    mma16816(acc[ma][nt * 2 + 1], ahf[ma], bhf[2], bhf[3]);
                    mma16816(acc[ma][nt * 2 + 1], ahf[ma], blf[2], blf[3]);
                    mma16816(acc[ma][nt * 2 + 1], alf[ma], bhf[2], bhf[3]);
                }
            }
        }
        __syncthreads();
    }

    // ---- epilogue ----
#pragma unroll
    for (int ma = 0; ma < 2; ma++) {
        int row = bm + wm * 32 + ma * 16 + (lane >> 2);
#pragma unroll
        for (int na = 0; na < 8; na++) {
            int col = bn + wn * 64 + na * 8 + (lane & 3) * 2;
            *(float2*)(C + (size_t)row * N + col) =
                make_float2(acc[ma][na][0], acc[ma][na][1]);
            *(float2*)(C + (size_t)(row + 8) * N + col) =
                make_float2(acc[ma][na][2], acc[ma][na][3]);
        }
    }
}

// ---------------------------------------------------------------------------
// RoPE table + apply
// ---------------------------------------------------------------------------
__global__ void rope_table_kernel() {
    int i = blockIdx.x * blockDim.x + threadIdx.x;
    if (i >= S * 64) return;
    int j = i & 63;
    int s = i >> 6;
    double ifd = exp(-((double)(2 * j) / 128.0) * log(10000.0));
    float invf = (float)ifd;
    float ang = (float)s * invf;
    double cd, sd;
    sincos((double)ang, &sd, &cd);
    g_rc[i] = (float)cd;
    g_rs[i] = (float)sd;
}

__global__ void rope_apply_kernel(float* __restrict__ x, int heads, int total) {
    int i = blockIdx.x * blockDim.x + threadIdx.x;
    if (i >= total) return;
    int j = i & 63;
    int rest = i >> 6;
    int h = rest % heads;
    int bs = rest / heads;
    int s = bs & (S - 1);
    float c = g_rc[s * 64 + j];
    float sn = g_rs[s * 64 + j];
    float* base = x + ((size_t)bs * heads + h) * HD;
    float x1 = base[j], x2 = base[j + 64];
    base[j]      = x1 * c - x2 * sn;
    base[j + 64] = x2 * c + x1 * sn;
}

// ---------------------------------------------------------------------------
// Per-chunk K mean
// ---------------------------------------------------------------------------
__global__ void kmean_kernel() {
    int id = blockIdx.x;
    int kvh = id & 3;
    int n = (id >> 2) & 7;
    int b = id >> 5;
    int d = threadIdx.x;
    const float* base = g_K + (((size_t)b * S + n * CHUNK) * NKV + kvh) * HD + d;
    float s = 0.f;
#pragma unroll 8
    for (int i = 0; i < CHUNK; i++) s += base[(size_t)i * NKV * HD];
    g_kmean[((b * NCH + n) * NKV + kvh) * HD + d] = s * (1.0f / CHUNK);
}

// ---------------------------------------------------------------------------
// Gate + top-k chunk selection. One warp per query.
// ---------------------------------------------------------------------------
__global__ void select_kernel() {
    int w = blockIdx.x * (blockDim.x >> 5) + (threadIdx.x >> 5);
    int lane = threadIdx.x & 31;
    int s = w & (S - 1);
    int h = (w >> 11) & (NH - 1);
    int b = w >> 15;
    int kvh = h >> 2;
    int qc = s >> 8;

    const float* q = g_Q + (((size_t)b * S + s) * NH + h) * HD;
    float4 qv = *(const float4*)(q + lane * 4);
    float g[8];
    for (int n = 0; n < qc; n++) {
        const float* km = g_kmean + ((b * NCH + n) * NKV + kvh) * HD;
        float4 kv = *(const float4*)(km + lane * 4);
        float p = qv.x * kv.x + qv.y * kv.y + qv.z * kv.z + qv.w * kv.w;
#pragma unroll
        for (int o = 16; o; o >>= 1) p += __shfl_xor_sync(0xffffffffu, p, o);
        g[n] = p;
    }
    if (lane == 0) {
        unsigned sel = 1u << qc;
        for (int it = 0; it < 3; it++) {
            float best = 0.f;
            int bi = -1;
            for (int n = 0; n < qc; n++)
                if (!((sel >> n) & 1) && (bi < 0 || g[n] > best)) { best = g[n]; bi = n; }
            if (bi >= 0) sel |= 1u << bi;
        }
        g_sel[w] = sel;
    }
}

// ---------------------------------------------------------------------------
// Tiled sparse flash attention (unchanged; FFMA-bound, ~1.3ms)
// ---------------------------------------------------------------------------
#define QS_STRIDE 132
#define KS_STRIDE 129
#define PS_STRIDE 68
#define ATTN_SMEM_FLOATS (QT * QS_STRIDE + KT * KS_STRIDE + KT * HD + KT * PS_STRIDE + 3 * QT + QT + 8)

__global__ __launch_bounds__(256)
void attn_tile_kernel() {
    extern __shared__ float sm[];
    float* Qs = sm;
    float* Ks = Qs + QT * QS_STRIDE;
    float* Vs = Ks + KT * KS_STRIDE;
    float* Ps = Vs + KT * HD;
    float* m_s = Ps + KT * PS_STRIDE;
    float* l_s = m_s + QT;
    float* scl = l_s + QT;
    unsigned* selq = (unsigned*)(scl + QT);
    unsigned* selu_p = selq + QT;

    int qt = gridDim.x - 1 - blockIdx.x;
    int h = blockIdx.y, b = blockIdx.z;
    int tid = threadIdx.x;
    int kvh = h >> 2;
    int s0 = qt * QT;
    int qc = s0 >> 8;

    {
        int q = tid >> 2, part = tid & 3;
        const float* qr = g_Q + (((size_t)b * S + s0 + q) * NH + h) * HD + part * 32;
#pragma unroll
        for (int i = 0; i < 8; i++)
            *(float4*)&Qs[q * QS_STRIDE + part * 32 + i * 4] = *(const float4*)(qr + i * 4);
    }
    if (tid == 0) *selu_p = 0;
    __syncthreads();
    if (tid < QT) {
        unsigned sv = g_sel[(((size_t)b * NH + h) << 11) + s0 + tid];
        selq[tid] = sv;
        atomicOr(selu_p, sv);
        m_s[tid] = -1e30f;
        l_s[tid] = 0.f;
    }
    __syncthreads();
    unsigned selu = *selu_p;

    float acc[4][8];
#pragma unroll
    for (int i = 0; i < 4; i++)
#pragma unroll
        for (int j = 0; j < 8; j++) acc[i][j] = 0.f;

    const float scale = 0.08838834764831845f;
    int nkt = (s0 >> 5) + 2;

    int qb = (tid >> 4) * 4;
    int kb = (tid & 15) * 2;
    int qg = tid >> 4;
    int dg = tid & 15;

    for (int kt = 0; kt < nkt; kt++) {
        int n = kt >> 3;
        if (n < qc && !((selu >> n) & 1)) continue;

        {
            int k = tid >> 3, part = tid & 7;
            size_t row = (((size_t)b * S + kt * KT + k) * NKV + kvh) * (size_t)HD;
            const float* kr = g_K + row + part * 16;
            const float* vr = g_V + row + part * 16;
#pragma unroll
            for (int i = 0; i < 4; i++) {
                float4 a = *(const float4*)(kr + i * 4);
                Ks[k * KS_STRIDE + part * 16 + i * 4 + 0] = a.x;
                Ks[k * KS_STRIDE + part * 16 + i * 4 + 1] = a.y;
                Ks[k * KS_STRIDE + part * 16 + i * 4 + 2] = a.z;
                Ks[k * KS_STRIDE + part * 16 + i * 4 + 3] = a.w;
                *(float4*)&Vs[k * HD + part * 16 + i * 4] = *(const float4*)(vr + i * 4);
            }
        }
        __syncthreads();

        float c00 = 0.f, c01 = 0.f, c10 = 0.f, c11 = 0.f;
        float c20 = 0.f, c21 = 0.f, c30 = 0.f, c31 = 0.f;
#pragma unroll 4
        for (int d = 0; d < HD; d++) {
            float b0 = Ks[(kb + 0) * KS_STRIDE + d];
            float b1 = Ks[(kb + 1) * KS_STRIDE + d];
            float r0 = Qs[(qb + 0) * QS_STRIDE + d];
            float r1 = Qs[(qb + 1) * QS_STRIDE + d];
            float r2 = Qs[(qb + 2) * QS_STRIDE + d];
            float r3 = Qs[(qb + 3) * QS_STRIDE + d];
            c00 += r0 * b0; c01 += r0 * b1;
            c10 += r1 * b0; c11 += r1 * b1;
            c20 += r2 * b0; c21 += r2 * b1;
            c30 += r3 * b0; c31 += r3 * b1;
        }
        {
            float cs[4][2] = {{c00, c01}, {c10, c11}, {c20, c21}, {c30, c31}};
#pragma unroll
            for (int i = 0; i < 4; i++) {
#pragma unroll
                for (int j = 0; j < 2; j++) {
                    int q = qb + i, k = kb + j;
                    int tg = kt * KT + k;
                    float v = cs[i][j] * scale;
                    bool ok = (n < qc) ? ((selq[q] >> n) & 1) : (tg <= s0 + q);
                    Ps[k * PS_STRIDE + q] = ok ? v : -3.0e38f;
                }
            }
        }
        __syncthreads();

        if (tid < QT) {
            float mo = m_s[tid];
            float mx = mo;
#pragma unroll 8
            for (int k = 0; k < KT; k++) mx = fmaxf(mx, Ps[k * PS_STRIDE + tid]);
            float mul = __expf(mo - mx);
            float sum = 0.f;
#pragma unroll 8
            for (int k = 0; k < KT; k++) {
                float p = __expf(Ps[k * PS_STRIDE + tid] - mx);
                Ps[k * PS_STRIDE + tid] = p;
                sum += p;
            }
            l_s[tid] = l_s[tid] * mul + sum;
            m_s[tid] = mx;
            scl[tid] = mul;
        }
        __syncthreads();

        {
            float f0 = scl[qg * 4 + 0], f1 = scl[qg * 4 + 1];
            float f2 = scl[qg * 4 + 2], f3 = scl[qg * 4 + 3];
#pragma unroll
            for (int j = 0; j < 8; j++) {
                acc[0][j] *= f0; acc[1][j] *= f1;
                acc[2][j] *= f2; acc[3][j] *= f3;
            }
#pragma unroll 2
            for (int k = 0; k < KT; k++) {
                float4 p4 = *(float4*)&Ps[k * PS_STRIDE + qg * 4];
                float4 v0 = *(float4*)&Vs[k * HD + dg * 8];
                float4 v1 = *(float4*)&Vs[k * HD + dg * 8 + 4];
                acc[0][0] += p4.x * v0.x; acc[0][1] += p4.x * v0.y;
                acc[0][2] += p4.x * v0.z; acc[0][3] += p4.x * v0.w;
                acc[0][4] += p4.x * v1.x; acc[0][5] += p4.x * v1.y;
                acc[0][6] += p4.x * v1.z; acc[0][7] += p4.x * v1.w;
                acc[1][0] += p4.y * v0.x; acc[1][1] += p4.y * v0.y;
                acc[1][2] += p4.y * v0.z; acc[1][3] += p4.y * v0.w;
                acc[1][4] += p4.y * v1.x; acc[1][5] += p4.y * v1.y;
                acc[1][6] += p4.y * v1.z; acc[1][7] += p4.y * v1.w;
                acc[2][0] += p4.z * v0.x; acc[2][1] += p4.z * v0.y;
                acc[2][2] += p4.z * v0.z; acc[2][3] += p4.z * v0.w;
                acc[2][4] += p4.z * v1.x; acc[2][5] += p4.z * v1.y;
                acc[2][6] += p4.z * v1.z; acc[2][7] += p4.z * v1.w;
                acc[3][0] += p4.w * v0.x; acc[3][1] += p4.w * v0.y;
                acc[3][2] += p4.w * v0.z; acc[3][3] += p4.w * v0.w;
                acc[3][4] += p4.w * v1.x; acc[3][5] += p4.w * v1.y;
                acc[3][6] += p4.w * v1.z; acc[3][7] += p4.w * v1.w;
            }
        }
        __syncthreads();
    }

#pragma unroll
    for (int i = 0; i < 4; i++) {
        int q = qg * 4 + i;
        float inv = 1.0f / l_s[q];
        float* o = g_O + (((size_t)b * S + s0 + q) * NH + h) * HD + dg * 8;
        float4 w0 = make_float4(acc[i][0] * inv, acc[i][1] * inv, acc[i][2] * inv, acc[i][3] * inv);
        float4 w1 = make_float4(acc[i][4] * inv, acc[i][5] * inv, acc[i][6] * inv, acc[i][7] * inv);
        *(float4*)o = w0;
        *(float4*)(o + 4) = w1;
    }
}

// ---------------------------------------------------------------------------
extern "C" void kernel_launch(void* const* d_in, const int* in_sizes, int n_in,
                              void* d_out, int out_size) {
    const float* x  = (const float*)d_in[0];
    const float* wq = (const float*)d_in[1];
    const float* wk = (const float*)d_in[2];
    const float* wv = (const float*)d_in[3];
    const float* wo = (const float*)d_in[4];
    float* out = (float*)d_out;

    float *Q, *K, *V, *O;
    cudaGetSymbolAddress((void**)&Q, g_Q);
    cudaGetSymbolAddress((void**)&K, g_K);
    cudaGetSymbolAddress((void**)&V, g_V);
    cudaGetSymbolAddress((void**)&O, g_O);

    __nv_bfloat16 *xh, *xl, *wqh, *wql, *wkh, *wkl, *wvh, *wvl, *woh, *wol, *oh, *ol;
    cudaGetSymbolAddress((void**)&xh, g_xh);
    cudaGetSymbolAddress((void**)&xl, g_xl);
    cudaGetSymbolAddress((void**)&wqh, g_wqh);
    cudaGetSymbolAddress((void**)&wql, g_wql);
    cudaGetSymbolAddress((void**)&wkh, g_wkh);
    cudaGetSymbolAddress((void**)&wkl, g_wkl);
    cudaGetSymbolAddress((void**)&wvh, g_wvh);
    cudaGetSymbolAddress((void**)&wvl, g_wvl);
    cudaGetSymbolAddress((void**)&woh, g_woh);
    cudaGetSymbolAddress((void**)&wol, g_wol);
    cudaGetSymbolAddress((void**)&oh, g_oh);
    cudaGetSymbolAddress((void**)&ol, g_ol);

    const int M = B * S;  // 4096
    const int attn_smem = ATTN_SMEM_FLOATS * 4;
    cudaFuncSetAttribute(attn_tile_kernel,
                         cudaFuncAttributeMaxDynamicSharedMemorySize, attn_smem);

    rope_table_kernel<<<(S * 64 + 255) / 256, 256>>>();

    // pre-split inputs/weights to bf16 hi/lo
    {
        int n4;
        n4 = (M * HID) / 4;
        split_kernel<<<(n4 + 255) / 256, 256>>>(x, xh, xl, n4);
        n4 = (HID * NH * HD) / 4;
        split_kernel<<<(n4 + 255) / 256, 256>>>(wq, wqh, wql, n4);
        n4 = (HID * NKV * HD) / 4;
        split_kernel<<<(n4 + 255) / 256, 256>>>(wk, wkh, wkl, n4);
        split_kernel<<<(n4 + 255) / 256, 256>>>(wv, wvh, wvl, n4);
        n4 = (NH * HD * HID) / 4;
        split_kernel<<<(n4 + 255) / 256, 256>>>(wo, woh, wol, n4);
    }

    // projections (tensor-core bf16x3)
    gemm_mma<<<dim3((NH * HD) / GBN, M / GBM), 256>>>(xh, xl, wqh, wql, Q, M, NH * HD, HID);
    gemm_mma<<<dim3((NKV * HD) / GBN, M / GBM), 256>>>(xh, xl, wkh, wkl, K, M, NKV * HD, HID);
    gemm_mma<<<dim3((NKV * HD) / GBN, M / GBM), 256>>>(xh, xl, wvh, wvl, V, M, NKV * HD, HID);

    // RoPE apply
    {
        int totq = B * S * NH * 64;
        rope_apply_kernel<<<(totq + 255) / 256, 256>>>(Q, NH, totq);
        int totk = B * S * NKV * 64;
        rope_apply_kernel<<<(totk + 255) / 256, 256>>>(K, NKV, totk);
    }

    // chunk means + gate/top-k selection
    kmean_kernel<<<B * NCH * NKV, 128>>>();
    select_kernel<<<(B * NH * S) / 8, 256>>>();

    // tiled sparse attention
    attn_tile_kernel<<<dim3(S / QT, NH, B), 256, attn_smem>>>();

    // split O, then output projection (tensor-core bf16x3)
    {
        int n4 = (M * HID) / 4;
        split_kernel<<<(n4 + 255) / 256, 256>>>(O, oh, ol, n4);
    }
    gemm_mma<<<dim3(HID / GBN, M / GBM), 256>>>(oh, ol, woh, wol, out, M, HID, HID);
}

// round 5
// speedup vs baseline: 2.4388x; 1.1037x over previous
#include <cuda_runtime.h>
#include <cuda_bf16.h>
#include <math.h>
#include <stdint.h>

// Problem constants
#define B 2
#define S 2048
#define HID 2048
#define NH 16
#define NKV 4
#define HD 128
#define CHUNK 256
#define NCH 8

// Attention tiling
#define QT 64
#define KT 32

// Scratch (static device allocations; no cudaMalloc allowed)
__device__ float g_Q[(size_t)B * S * NH * HD];
__device__ float g_K[(size_t)B * S * NKV * HD];
__device__ float g_V[(size_t)B * S * NKV * HD];
__device__ float g_O[(size_t)B * S * NH * HD];
__device__ float g_kmean[(size_t)B * NCH * NKV * HD];
__device__ unsigned g_sel[(size_t)B * NH * S];
__device__ float g_rc[(size_t)S * 64];
__device__ float g_rs[(size_t)S * 64];

// bf16 hi/lo split copies (pre-split once; GEMMs read these)
__device__ __nv_bfloat16 g_xh[(size_t)B * S * HID];
__device__ __nv_bfloat16 g_xl[(size_t)B * S * HID];
__device__ __nv_bfloat16 g_wqh[(size_t)HID * NH * HD];
__device__ __nv_bfloat16 g_wql[(size_t)HID * NH * HD];
__device__ __nv_bfloat16 g_wkh[(size_t)HID * NKV * HD];
__device__ __nv_bfloat16 g_wkl[(size_t)HID * NKV * HD];
__device__ __nv_bfloat16 g_wvh[(size_t)HID * NKV * HD];
__device__ __nv_bfloat16 g_wvl[(size_t)HID * NKV * HD];
__device__ __nv_bfloat16 g_woh[(size_t)NH * HD * HID];
__device__ __nv_bfloat16 g_wol[(size_t)NH * HD * HID];
__device__ __nv_bfloat16 g_oh[(size_t)B * S * NH * HD];
__device__ __nv_bfloat16 g_ol[(size_t)B * S * NH * HD];

// ===========================================================================
// helpers
// ===========================================================================
__device__ __forceinline__ uint32_t smem_u32(const void* p) {
    uint32_t a;
    asm("{ .reg .u64 t; cvta.to.shared.u64 t, %1; cvt.u32.u64 %0, t; }"
        : "=r"(a) : "l"(p));
    return a;
}

__device__ __forceinline__ void ldsm4(uint32_t* r, uint32_t addr) {
    asm volatile("ldmatrix.sync.aligned.m8n8.x4.shared.b16 {%0,%1,%2,%3}, [%4];"
                 : "=r"(r[0]), "=r"(r[1]), "=r"(r[2]), "=r"(r[3]) : "r"(addr));
}
__device__ __forceinline__ void ldsm4t(uint32_t* r, uint32_t addr) {
    asm volatile("ldmatrix.sync.aligned.m8n8.x4.trans.shared.b16 {%0,%1,%2,%3}, [%4];"
                 : "=r"(r[0]), "=r"(r[1]), "=r"(r[2]), "=r"(r[3]) : "r"(addr));
}
__device__ __forceinline__ void mma16816(float* c, const uint32_t* a,
                                         uint32_t b0, uint32_t b1) {
    asm volatile(
        "mma.sync.aligned.m16n8k16.row.col.f32.bf16.bf16.f32 "
        "{%0,%1,%2,%3}, {%4,%5,%6,%7}, {%8,%9}, {%0,%1,%2,%3};"
        : "+f"(c[0]), "+f"(c[1]), "+f"(c[2]), "+f"(c[3])
        : "r"(a[0]), "r"(a[1]), "r"(a[2]), "r"(a[3]), "r"(b0), "r"(b1));
}

// exact fp32 -> (bf16 hi, bf16 lo)
__device__ __forceinline__ void split1(float a, __nv_bfloat16& h, __nv_bfloat16& l) {
    h = __float2bfloat16_rn(a);
    l = __float2bfloat16_rn(a - __bfloat162float(h));
}

// ---------------------------------------------------------------------------
// split kernel: fp32 -> bf16 hi + lo (float4 granular)
// ---------------------------------------------------------------------------
__global__ void split_kernel(const float* __restrict__ in,
                             __nv_bfloat16* __restrict__ hi,
                             __nv_bfloat16* __restrict__ lo, int n4) {
    int i = blockIdx.x * blockDim.x + threadIdx.x;
    if (i >= n4) return;
    float4 v = ((const float4*)in)[i];
    __nv_bfloat16 h0, h1, h2, h3, l0, l1, l2, l3;
    split1(v.x, h0, l0);
    split1(v.y, h1, l1);
    split1(v.z, h2, l2);
    split1(v.w, h3, l3);
    uint32_t ha = ((uint32_t)__bfloat16_as_ushort(h1) << 16) | __bfloat16_as_ushort(h0);
    uint32_t hb = ((uint32_t)__bfloat16_as_ushort(h3) << 16) | __bfloat16_as_ushort(h2);
    uint32_t la = ((uint32_t)__bfloat16_as_ushort(l1) << 16) | __bfloat16_as_ushort(l0);
    uint32_t lb = ((uint32_t)__bfloat16_as_ushort(l3) << 16) | __bfloat16_as_ushort(l2);
    ((uint2*)hi)[i] = make_uint2(ha, hb);
    ((uint2*)lo)[i] = make_uint2(la, lb);
}

// ===========================================================================
// bf16x3 GEMM via mma.sync (m16n8k16): C[M,N] = A[M,K] * W[K,N], fp32 out.
// Block 128x128xBK32, 256 threads, 8 warps (4 M x 2 N), warp tile 32x64.
// MMA issue is product-major across 8 independent accumulator targets so
// same-target MMAs are ~8 instructions apart (hides HMMA result latency).
// ===========================================================================
#define GBM 128
#define GBN 128
#define GBK 32

__global__ __launch_bounds__(256, 2)
void gemm_mma(const __nv_bfloat16* __restrict__ Ah, const __nv_bfloat16* __restrict__ Al,
              const __nv_bfloat16* __restrict__ Bh, const __nv_bfloat16* __restrict__ Bl,
              float* __restrict__ C, int M, int N, int K) {
    __shared__ __align__(16) __nv_bfloat16 Ash[128][40];   // stride 80B
    __shared__ __align__(16) __nv_bfloat16 Asl[128][40];
    __shared__ __align__(16) __nv_bfloat16 Bsh[32][136];   // stride 272B
    __shared__ __align__(16) __nv_bfloat16 Bsl[32][136];

    int tid = threadIdx.x;
    int lane = tid & 31, wid = tid >> 5;
    int wm = wid & 3, wn = wid >> 2;
    int bm = blockIdx.y * GBM, bn = blockIdx.x * GBN;

    float acc[2][8][4];
#pragma unroll
    for (int i = 0; i < 2; i++)
#pragma unroll
        for (int j = 0; j < 8; j++)
#pragma unroll
            for (int k = 0; k < 4; k++) acc[i][j][k] = 0.f;

    uint32_t ash = smem_u32(Ash), asl = smem_u32(Asl);
    uint32_t bsh = smem_u32(Bsh), bsl = smem_u32(Bsl);

    int l15 = lane & 15, l16 = lane >> 4;
    uint32_t a_off = (uint32_t)(wm * 32 + l15) * 80 + l16 * 16;
    uint32_t b_off = (uint32_t)(((lane >> 3) & 1) * 8 + (lane & 7)) * 272
                   + wn * 128 + l16 * 16;

    for (int k0 = 0; k0 < K; k0 += GBK) {
        // ---- stage tiles ----
#pragma unroll
        for (int i = 0; i < 4; i++) {
            int s = tid + i * 256;
            int row = s >> 3, q = s & 7;
            size_t g = (size_t)(bm + row) * K + k0 + q * 4;
            *(uint2*)&Ash[row][q * 4] = *(const uint2*)(Ah + g);
            *(uint2*)&Asl[row][q * 4] = *(const uint2*)(Al + g);
        }
#pragma unroll
        for (int i = 0; i < 2; i++) {
            int s = tid + i * 256;
            int row = s >> 4, q = s & 15;
            size_t g = (size_t)(k0 + row) * N + bn + q * 8;
            *(uint4*)&Bsh[row][q * 8] = *(const uint4*)(Bh + g);
            *(uint4*)&Bsl[row][q * 8] = *(const uint4*)(Bl + g);
        }
        __syncthreads();

#pragma unroll
        for (int ka = 0; ka < 2; ka++) {
            uint32_t ahf[2][4], alf[2][4];
            ldsm4(ahf[0], ash + a_off + ka * 32);
            ldsm4(ahf[1], ash + a_off + ka * 32 + 16 * 80);
            ldsm4(alf[0], asl + a_off + ka * 32);
            ldsm4(alf[1], asl + a_off + ka * 32 + 16 * 80);
#pragma unroll
            for (int nh2 = 0; nh2 < 2; nh2++) {
                // hold two adjacent 16-col B groups -> 8 indep acc targets
                uint32_t bhf[2][4], blf[2][4];
                uint32_t bo = b_off + ka * 16 * 272 + nh2 * 64;
                ldsm4t(bhf[0], bsh + bo);
                ldsm4t(bhf[1], bsh + bo + 32);
                ldsm4t(blf[0], bsl + bo);
                ldsm4t(blf[1], bsl + bo + 32);
                // product-major issue: hh over 8 targets, hl over 8, lh over 8
#pragma unroll
                for (int j = 0; j < 2; j++)
#pragma unroll
                    for (int ma = 0; ma < 2; ma++)
#pragma unroll
                        for (int sub = 0; sub < 2; sub++)
                            mma16816(acc[ma][(nh2 * 2 + j) * 2 + sub], ahf[ma],
                                     bhf[j][sub * 2], bhf[j][sub * 2 + 1]);
#pragma unroll
                for (int j = 0; j < 2; j++)
#pragma unroll
                    for (int ma = 0; ma < 2; ma++)
#pragma unroll
                        for (int sub = 0; sub < 2; sub++)
                            mma16816(acc[ma][(nh2 * 2 + j) * 2 + sub], ahf[ma],
                                     blf[j][sub * 2], blf[j][sub * 2 + 1]);
#pragma unroll
                for (int j = 0; j < 2; j++)
#pragma unroll
                    for (int ma = 0; ma < 2; ma++)
#pragma unroll
                        for (int sub = 0; sub < 2; sub++)
                            mma16816(acc[ma][(nh2 * 2 + j) * 2 + sub], alf[ma],
                                     bhf[j][sub * 2], bhf[j][sub * 2 + 1]);
            }
        }
        __syncthreads();
    }

    // ---- epilogue ----
#pragma unroll
    for (int ma = 0; ma < 2; ma++) {
        int row = bm + wm * 32 + ma * 16 + (lane >> 2);
#pragma unroll
        for (int na = 0; na < 8; na++) {
            int col = bn + wn * 64 + na * 8 + (lane & 3) * 2;
            *(float2*)(C + (size_t)row * N + col) =
                make_float2(acc[ma][na][0], acc[ma][na][1]);
            *(float2*)(C + (size_t)(row + 8) * N + col) =
                make_float2(acc[ma][na][2], acc[ma][na][3]);
        }
    }
}

// ---------------------------------------------------------------------------
// RoPE table + apply
// ---------------------------------------------------------------------------
__global__ void rope_table_kernel() {
    int i = blockIdx.x * blockDim.x + threadIdx.x;
    if (i >= S * 64) return;
    int j = i & 63;
    int s = i >> 6;
    double ifd = exp(-((double)(2 * j) / 128.0) * log(10000.0));
    float invf = (float)ifd;
    float ang = (float)s * invf;
    double cd, sd;
    sincos((double)ang, &sd, &cd);
    g_rc[i] = (float)cd;
    g_rs[i] = (float)sd;
}

__global__ void rope_apply_kernel(float* __restrict__ x, int heads, int total) {
    int i = blockIdx.x * blockDim.x + threadIdx.x;
    if (i >= total) return;
    int j = i & 63;
    int rest = i >> 6;
    int h = rest % heads;
    int bs = rest / heads;
    int s = bs & (S - 1);
    float c = g_rc[s * 64 + j];
    float sn = g_rs[s * 64 + j];
    float* base = x + ((size_t)bs * heads + h) * HD;
    float x1 = base[j], x2 = base[j + 64];
    base[j]      = x1 * c - x2 * sn;
    base[j + 64] = x2 * c + x1 * sn;
}

// ---------------------------------------------------------------------------
// Per-chunk K mean
// ---------------------------------------------------------------------------
__global__ void kmean_kernel() {
    int id = blockIdx.x;
    int kvh = id & 3;
    int n = (id >> 2) & 7;
    int b = id >> 5;
    int d = threadIdx.x;
    const float* base = g_K + (((size_t)b * S + n * CHUNK) * NKV + kvh) * HD + d;
    float s = 0.f;
#pragma unroll 8
    for (int i = 0; i < CHUNK; i++) s += base[(size_t)i * NKV * HD];
    g_kmean[((b * NCH + n) * NKV + kvh) * HD + d] = s * (1.0f / CHUNK);
}

// ---------------------------------------------------------------------------
// Gate + top-k chunk selection. One warp per query.
// ---------------------------------------------------------------------------
__global__ void select_kernel() {
    int w = blockIdx.x * (blockDim.x >> 5) + (threadIdx.x >> 5);
    int lane = threadIdx.x & 31;
    int s = w & (S - 1);
    int h = (w >> 11) & (NH - 1);
    int b = w >> 15;
    int kvh = h >> 2;
    int qc = s >> 8;

    const float* q = g_Q + (((size_t)b * S + s) * NH + h) * HD;
    float4 qv = *(const float4*)(q + lane * 4);
    float g[8];
    for (int n = 0; n < qc; n++) {
        const float* km = g_kmean + ((b * NCH + n) * NKV + kvh) * HD;
        float4 kv = *(const float4*)(km + lane * 4);
        float p = qv.x * kv.x + qv.y * kv.y + qv.z * kv.z + qv.w * kv.w;
#pragma unroll
        for (int o = 16; o; o >>= 1) p += __shfl_xor_sync(0xffffffffu, p, o);
        g[n] = p;
    }
    if (lane == 0) {
        unsigned sel = 1u << qc;
        for (int it = 0; it < 3; it++) {
            float best = 0.f;
            int bi = -1;
            for (int n = 0; n < qc; n++)
                if (!((sel >> n) & 1) && (bi < 0 || g[n] > best)) { best = g[n]; bi = n; }
            if (bi >= 0) sel |= 1u << bi;
        }
        g_sel[w] = sel;
    }
}

// ---------------------------------------------------------------------------
// Tiled sparse flash attention (unchanged; FFMA-bound, ~1.3ms)
// ---------------------------------------------------------------------------
#define QS_STRIDE 132
#define KS_STRIDE 129
#define PS_STRIDE 68
#define ATTN_SMEM_FLOATS (QT * QS_STRIDE + KT * KS_STRIDE + KT * HD + KT * PS_STRIDE + 3 * QT + QT + 8)

__global__ __launch_bounds__(256)
void attn_tile_kernel() {
    extern __shared__ float sm[];
    float* Qs = sm;
    float* Ks = Qs + QT * QS_STRIDE;
    float* Vs = Ks + KT * KS_STRIDE;
    float* Ps = Vs + KT * HD;
    float* m_s = Ps + KT * PS_STRIDE;
    float* l_s = m_s + QT;
    float* scl = l_s + QT;
    unsigned* selq = (unsigned*)(scl + QT);
    unsigned* selu_p = selq + QT;

    int qt = gridDim.x - 1 - blockIdx.x;
    int h = blockIdx.y, b = blockIdx.z;
    int tid = threadIdx.x;
    int kvh = h >> 2;
    int s0 = qt * QT;
    int qc = s0 >> 8;

    {
        int q = tid >> 2, part = tid & 3;
        const float* qr = g_Q + (((size_t)b * S + s0 + q) * NH + h) * HD + part * 32;
#pragma unroll
        for (int i = 0; i < 8; i++)
            *(float4*)&Qs[q * QS_STRIDE + part * 32 + i * 4] = *(const float4*)(qr + i * 4);
    }
    if (tid == 0) *selu_p = 0;
    __syncthreads();
    if (tid < QT) {
        unsigned sv = g_sel[(((size_t)b * NH + h) << 11) + s0 + tid];
        selq[tid] = sv;
        atomicOr(selu_p, sv);
        m_s[tid] = -1e30f;
        l_s[tid] = 0.f;
    }
    __syncthreads();
    unsigned selu = *selu_p;

    float acc[4][8];
#pragma unroll
    for (int i = 0; i < 4; i++)
#pragma unroll
        for (int j = 0; j < 8; j++) acc[i][j] = 0.f;

    const float scale = 0.08838834764831845f;
    int nkt = (s0 >> 5) + 2;

    int qb = (tid >> 4) * 4;
    int kb = (tid & 15) * 2;
    int qg = tid >> 4;
    int dg = tid & 15;

    for (int kt = 0; kt < nkt; kt++) {
        int n = kt >> 3;
        if (n < qc && !((selu >> n) & 1)) continue;

        {
            int k = tid >> 3, part = tid & 7;
            size_t row = (((size_t)b * S + kt * KT + k) * NKV + kvh) * (size_t)HD;
            const float* kr = g_K + row + part * 16;
            const float* vr = g_V + row + part * 16;
#pragma unroll
            for (int i = 0; i < 4; i++) {
                float4 a = *(const float4*)(kr + i * 4);
                Ks[k * KS_STRIDE + part * 16 + i * 4 + 0] = a.x;
                Ks[k * KS_STRIDE + part * 16 + i * 4 + 1] = a.y;
                Ks[k * KS_STRIDE + part * 16 + i * 4 + 2] = a.z;
                Ks[k * KS_STRIDE + part * 16 + i * 4 + 3] = a.w;
                *(float4*)&Vs[k * HD + part * 16 + i * 4] = *(const float4*)(vr + i * 4);
            }
        }
        __syncthreads();

        float c00 = 0.f, c01 = 0.f, c10 = 0.f, c11 = 0.f;
        float c20 = 0.f, c21 = 0.f, c30 = 0.f, c31 = 0.f;
#pragma unroll 4
        for (int d = 0; d < HD; d++) {
            float b0 = Ks[(kb + 0) * KS_STRIDE + d];
            float b1 = Ks[(kb + 1) * KS_STRIDE + d];
            float r0 = Qs[(qb + 0) * QS_STRIDE + d];
            float r1 = Qs[(qb + 1) * QS_STRIDE + d];
            float r2 = Qs[(qb + 2) * QS_STRIDE + d];
            float r3 = Qs[(qb + 3) * QS_STRIDE + d];
            c00 += r0 * b0; c01 += r0 * b1;
            c10 += r1 * b0; c11 += r1 * b1;
            c20 += r2 * b0; c21 += r2 * b1;
            c30 += r3 * b0; c31 += r3 * b1;
        }
        {
            float cs[4][2] = {{c00, c01}, {c10, c11}, {c20, c21}, {c30, c31}};
#pragma unroll
            for (int i = 0; i < 4; i++) {
#pragma unroll
                for (int j = 0; j < 2; j++) {
                    int q = qb + i, k = kb + j;
                    int tg = kt * KT + k;
                    float v = cs[i][j] * scale;
                    bool ok = (n < qc) ? ((selq[q] >> n) & 1) : (tg <= s0 + q);
                    Ps[k * PS_STRIDE + q] = ok ? v : -3.0e38f;
                }
            }
        }
        __syncthreads();

        if (tid < QT) {
            float mo = m_s[tid];
            float mx = mo;
#pragma unroll 8
            for (int k = 0; k < KT; k++) mx = fmaxf(mx, Ps[k * PS_STRIDE + tid]);
            float mul = __expf(mo - mx);
            float sum = 0.f;
#pragma unroll 8
            for (int k = 0; k < KT; k++) {
                float p = __expf(Ps[k * PS_STRIDE + tid] - mx);
                Ps[k * PS_STRIDE + tid] = p;
                sum += p;
            }
            l_s[tid] = l_s[tid] * mul + sum;
            m_s[tid] = mx;
            scl[tid] = mul;
        }
        __syncthreads();

        {
            float f0 = scl[qg * 4 + 0], f1 = scl[qg * 4 + 1];
            float f2 = scl[qg * 4 + 2], f3 = scl[qg * 4 + 3];
#pragma unroll
            for (int j = 0; j < 8; j++) {
                acc[0][j] *= f0; acc[1][j] *= f1;
                acc[2][j] *= f2; acc[3][j] *= f3;
            }
#pragma unroll 2
            for (int k = 0; k < KT; k++) {
                float4 p4 = *(float4*)&Ps[k * PS_STRIDE + qg * 4];
                float4 v0 = *(float4*)&Vs[k * HD + dg * 8];
                float4 v1 = *(float4*)&Vs[k * HD + dg * 8 + 4];
                acc[0][0] += p4.x * v0.x; acc[0][1] += p4.x * v0.y;
                acc[0][2] += p4.x * v0.z; acc[0][3] += p4.x * v0.w;
                acc[0][4] += p4.x * v1.x; acc[0][5] += p4.x * v1.y;
                acc[0][6] += p4.x * v1.z; acc[0][7] += p4.x * v1.w;
                acc[1][0] += p4.y * v0.x; acc[1][1] += p4.y * v0.y;
                acc[1][2] += p4.y * v0.z; acc[1][3] += p4.y * v0.w;
                acc[1][4] += p4.y * v1.x; acc[1][5] += p4.y * v1.y;
                acc[1][6] += p4.y * v1.z; acc[1][7] += p4.y * v1.w;
                acc[2][0] += p4.z * v0.x; acc[2][1] += p4.z * v0.y;
                acc[2][2] += p4.z * v0.z; acc[2][3] += p4.z * v0.w;
                acc[2][4] += p4.z * v1.x; acc[2][5] += p4.z * v1.y;
                acc[2][6] += p4.z * v1.z; acc[2][7] += p4.z * v1.w;
                acc[3][0] += p4.w * v0.x; acc[3][1] += p4.w * v0.y;
                acc[3][2] += p4.w * v0.z; acc[3][3] += p4.w * v0.w;
                acc[3][4] += p4.w * v1.x; acc[3][5] += p4.w * v1.y;
                acc[3][6] += p4.w * v1.z; acc[3][7] += p4.w * v1.w;
            }
        }
        __syncthreads();
    }

#pragma unroll
    for (int i = 0; i < 4; i++) {
        int q = qg * 4 + i;
        float inv = 1.0f / l_s[q];
        float* o = g_O + (((size_t)b * S + s0 + q) * NH + h) * HD + dg * 8;
        float4 w0 = make_float4(acc[i][0] * inv, acc[i][1] * inv, acc[i][2] * inv, acc[i][3] * inv);
        float4 w1 = make_float4(acc[i][4] * inv, acc[i][5] * inv, acc[i][6] * inv, acc[i][7] * inv);
        *(float4*)o = w0;
        *(float4*)(o + 4) = w1;
    }
}

// ---------------------------------------------------------------------------
extern "C" void kernel_launch(void* const* d_in, const int* in_sizes, int n_in,
                              void* d_out, int out_size) {
    const float* x  = (const float*)d_in[0];
    const float* wq = (const float*)d_in[1];
    const float* wk = (const float*)d_in[2];
    const float* wv = (const float*)d_in[3];
    const float* wo = (const float*)d_in[4];
    float* out = (float*)d_out;

    float *Q, *K, *V, *O;
    cudaGetSymbolAddress((void**)&Q, g_Q);
    cudaGetSymbolAddress((void**)&K, g_K);
    cudaGetSymbolAddress((void**)&V, g_V);
    cudaGetSymbolAddress((void**)&O, g_O);

    __nv_bfloat16 *xh, *xl, *wqh, *wql, *wkh, *wkl, *wvh, *wvl, *woh, *wol, *oh, *ol;
    cudaGetSymbolAddress((void**)&xh, g_xh);
    cudaGetSymbolAddress((void**)&xl, g_xl);
    cudaGetSymbolAddress((void**)&wqh, g_wqh);
    cudaGetSymbolAddress((void**)&wql, g_wql);
    cudaGetSymbolAddress((void**)&wkh, g_wkh);
    cudaGetSymbolAddress((void**)&wkl, g_wkl);
    cudaGetSymbolAddress((void**)&wvh, g_wvh);
    cudaGetSymbolAddress((void**)&wvl, g_wvl);
    cudaGetSymbolAddress((void**)&woh, g_woh);
    cudaGetSymbolAddress((void**)&wol, g_wol);
    cudaGetSymbolAddress((void**)&oh, g_oh);
    cudaGetSymbolAddress((void**)&ol, g_ol);

    const int M = B * S;  // 4096
    const int attn_smem = ATTN_SMEM_FLOATS * 4;
    cudaFuncSetAttribute(attn_tile_kernel,
                         cudaFuncAttributeMaxDynamicSharedMemorySize, attn_smem);

    rope_table_kernel<<<(S * 64 + 255) / 256, 256>>>();

    // pre-split inputs/weights to bf16 hi/lo
    {
        int n4;
        n4 = (M * HID) / 4;
        split_kernel<<<(n4 + 255) / 256, 256>>>(x, xh, xl, n4);
        n4 = (HID * NH * HD) / 4;
        split_kernel<<<(n4 + 255) / 256, 256>>>(wq, wqh, wql, n4);
        n4 = (HID * NKV * HD) / 4;
        split_kernel<<<(n4 + 255) / 256, 256>>>(wk, wkh, wkl, n4);
        split_kernel<<<(n4 + 255) / 256, 256>>>(wv, wvh, wvl, n4);
        n4 = (NH * HD * HID) / 4;
        split_kernel<<<(n4 + 255) / 256, 256>>>(wo, woh, wol, n4);
    }

    // projections (tensor-core bf16x3)
    gemm_mma<<<dim3((NH * HD) / GBN, M / GBM), 256>>>(xh, xl, wqh, wql, Q, M, NH * HD, HID);
    gemm_mma<<<dim3((NKV * HD) / GBN, M / GBM), 256>>>(xh, xl, wkh, wkl, K, M, NKV * HD, HID);
    gemm_mma<<<dim3((NKV * HD) / GBN, M / GBM), 256>>>(xh, xl, wvh, wvl, V, M, NKV * HD, HID);

    // RoPE apply
    {
        int totq = B * S * NH * 64;
        rope_apply_kernel<<<(totq + 255) / 256, 256>>>(Q, NH, totq);
        int totk = B * S * NKV * 64;
        rope_apply_kernel<<<(totk + 255) / 256, 256>>>(K, NKV, totk);
    }

    // chunk means + gate/top-k selection
    kmean_kernel<<<B * NCH * NKV, 128>>>();
    select_kernel<<<(B * NH * S) / 8, 256>>>();

    // tiled sparse attention
    attn_tile_kernel<<<dim3(S / QT, NH, B), 256, attn_smem>>>();

    // split O, then output projection (tensor-core bf16x3)
    {
        int n4 = (M * HID) / 4;
        split_kernel<<<(n4 + 255) / 256, 256>>>(O, oh, ol, n4);
    }
    gemm_mma<<<dim3(HID / GBN, M / GBM), 256>>>(oh, ol, woh, wol, out, M, HID, HID);
}

// round 6
// speedup vs baseline: 4.5747x; 1.8758x over previous
#include <cuda_runtime.h>
#include <cuda_bf16.h>
#include <math.h>
#include <stdint.h>

// Problem constants
#define B 2
#define S 2048
#define HID 2048
#define NH 16
#define NKV 4
#define HD 128
#define CHUNK 256
#define NCH 8

// Scratch (static device allocations; no cudaMalloc allowed)
__device__ float g_Q[(size_t)B * S * NH * HD];
__device__ float g_K[(size_t)B * S * NKV * HD];
__device__ float g_V[(size_t)B * S * NKV * HD];
__device__ float g_kmean[(size_t)B * NCH * NKV * HD];
__device__ unsigned g_sel[(size_t)B * NH * S];
__device__ float g_rc[(size_t)S * 64];
__device__ float g_rs[(size_t)S * 64];

// bf16 hi/lo split copies
__device__ __nv_bfloat16 g_xh[(size_t)B * S * HID];
__device__ __nv_bfloat16 g_xl[(size_t)B * S * HID];
__device__ __nv_bfloat16 g_wqh[(size_t)HID * NH * HD];
__device__ __nv_bfloat16 g_wql[(size_t)HID * NH * HD];
__device__ __nv_bfloat16 g_wkh[(size_t)HID * NKV * HD];
__device__ __nv_bfloat16 g_wkl[(size_t)HID * NKV * HD];
__device__ __nv_bfloat16 g_wvh[(size_t)HID * NKV * HD];
__device__ __nv_bfloat16 g_wvl[(size_t)HID * NKV * HD];
__device__ __nv_bfloat16 g_woh[(size_t)NH * HD * HID];
__device__ __nv_bfloat16 g_wol[(size_t)NH * HD * HID];
__device__ __nv_bfloat16 g_oh[(size_t)B * S * NH * HD];
__device__ __nv_bfloat16 g_ol[(size_t)B * S * NH * HD];
// post-RoPE bf16 splits for attention
__device__ __nv_bfloat16 g_Qh[(size_t)B * S * NH * HD];
__device__ __nv_bfloat16 g_Ql[(size_t)B * S * NH * HD];
__device__ __nv_bfloat16 g_Kh[(size_t)B * S * NKV * HD];
__device__ __nv_bfloat16 g_Kl[(size_t)B * S * NKV * HD];
__device__ __nv_bfloat16 g_Vh[(size_t)B * S * NKV * HD];
__device__ __nv_bfloat16 g_Vl[(size_t)B * S * NKV * HD];

// ===========================================================================
// helpers
// ===========================================================================
__device__ __forceinline__ uint32_t smem_u32(const void* p) {
    uint32_t a;
    asm("{ .reg .u64 t; cvta.to.shared.u64 t, %1; cvt.u32.u64 %0, t; }"
        : "=r"(a) : "l"(p));
    return a;
}

__device__ __forceinline__ void ldsm4(uint32_t* r, uint32_t addr) {
    asm volatile("ldmatrix.sync.aligned.m8n8.x4.shared.b16 {%0,%1,%2,%3}, [%4];"
                 : "=r"(r[0]), "=r"(r[1]), "=r"(r[2]), "=r"(r[3]) : "r"(addr));
}
__device__ __forceinline__ void ldsm4t(uint32_t* r, uint32_t addr) {
    asm volatile("ldmatrix.sync.aligned.m8n8.x4.trans.shared.b16 {%0,%1,%2,%3}, [%4];"
                 : "=r"(r[0]), "=r"(r[1]), "=r"(r[2]), "=r"(r[3]) : "r"(addr));
}
__device__ __forceinline__ void mma16816(float* c, const uint32_t* a,
                                         uint32_t b0, uint32_t b1) {
    asm volatile(
        "mma.sync.aligned.m16n8k16.row.col.f32.bf16.bf16.f32 "
        "{%0,%1,%2,%3}, {%4,%5,%6,%7}, {%8,%9}, {%0,%1,%2,%3};"
        : "+f"(c[0]), "+f"(c[1]), "+f"(c[2]), "+f"(c[3])
        : "r"(a[0]), "r"(a[1]), "r"(a[2]), "r"(a[3]), "r"(b0), "r"(b1));
}

__device__ __forceinline__ void split1(float a, __nv_bfloat16& h, __nv_bfloat16& l) {
    h = __float2bfloat16_rn(a);
    l = __float2bfloat16_rn(a - __bfloat162float(h));
}
__device__ __forceinline__ uint32_t packbf(__nv_bfloat16 lo, __nv_bfloat16 hi) {
    return ((uint32_t)__bfloat16_as_ushort(hi) << 16) | __bfloat16_as_ushort(lo);
}

// ---------------------------------------------------------------------------
// split kernel: fp32 -> bf16 hi + lo
// ---------------------------------------------------------------------------
__global__ void split_kernel(const float* __restrict__ in,
                             __nv_bfloat16* __restrict__ hi,
                             __nv_bfloat16* __restrict__ lo, int n4) {
    int i = blockIdx.x * blockDim.x + threadIdx.x;
    if (i >= n4) return;
    float4 v = ((const float4*)in)[i];
    __nv_bfloat16 h0, h1, h2, h3, l0, l1, l2, l3;
    split1(v.x, h0, l0);
    split1(v.y, h1, l1);
    split1(v.z, h2, l2);
    split1(v.w, h3, l3);
    ((uint2*)hi)[i] = make_uint2(packbf(h0, h1), packbf(h2, h3));
    ((uint2*)lo)[i] = make_uint2(packbf(l0, l1), packbf(l2, l3));
}

// ===========================================================================
// bf16x3 GEMM via mma.sync (unchanged from R5)
// ===========================================================================
#define GBM 128
#define GBN 128
#define GBK 32

__global__ __launch_bounds__(256, 2)
void gemm_mma(const __nv_bfloat16* __restrict__ Ah, const __nv_bfloat16* __restrict__ Al,
              const __nv_bfloat16* __restrict__ Bh, const __nv_bfloat16* __restrict__ Bl,
              float* __restrict__ C, int M, int N, int K) {
    __shared__ __align__(16) __nv_bfloat16 Ash[128][40];
    __shared__ __align__(16) __nv_bfloat16 Asl[128][40];
    __shared__ __align__(16) __nv_bfloat16 Bsh[32][136];
    __shared__ __align__(16) __nv_bfloat16 Bsl[32][136];

    int tid = threadIdx.x;
    int lane = tid & 31, wid = tid >> 5;
    int wm = wid & 3, wn = wid >> 2;
    int bm = blockIdx.y * GBM, bn = blockIdx.x * GBN;

    float acc[2][8][4];
#pragma unroll
    for (int i = 0; i < 2; i++)
#pragma unroll
        for (int j = 0; j < 8; j++)
#pragma unroll
            for (int k = 0; k < 4; k++) acc[i][j][k] = 0.f;

    uint32_t ash = smem_u32(Ash), asl = smem_u32(Asl);
    uint32_t bsh = smem_u32(Bsh), bsl = smem_u32(Bsl);

    int l15 = lane & 15, l16 = lane >> 4;
    uint32_t a_off = (uint32_t)(wm * 32 + l15) * 80 + l16 * 16;
    uint32_t b_off = (uint32_t)(((lane >> 3) & 1) * 8 + (lane & 7)) * 272
                   + wn * 128 + l16 * 16;

    for (int k0 = 0; k0 < K; k0 += GBK) {
#pragma unroll
        for (int i = 0; i < 4; i++) {
            int s = tid + i * 256;
            int row = s >> 3, q = s & 7;
            size_t g = (size_t)(bm + row) * K + k0 + q * 4;
            *(uint2*)&Ash[row][q * 4] = *(const uint2*)(Ah + g);
            *(uint2*)&Asl[row][q * 4] = *(const uint2*)(Al + g);
        }
#pragma unroll
        for (int i = 0; i < 2; i++) {
            int s = tid + i * 256;
            int row = s >> 4, q = s & 15;
            size_t g = (size_t)(k0 + row) * N + bn + q * 8;
            *(uint4*)&Bsh[row][q * 8] = *(const uint4*)(Bh + g);
            *(uint4*)&Bsl[row][q * 8] = *(const uint4*)(Bl + g);
        }
        __syncthreads();

#pragma unroll
        for (int ka = 0; ka < 2; ka++) {
            uint32_t ahf[2][4], alf[2][4];
            ldsm4(ahf[0], ash + a_off + ka * 32);
            ldsm4(ahf[1], ash + a_off + ka * 32 + 16 * 80);
            ldsm4(alf[0], asl + a_off + ka * 32);
            ldsm4(alf[1], asl + a_off + ka * 32 + 16 * 80);
#pragma unroll
            for (int nh2 = 0; nh2 < 2; nh2++) {
                uint32_t bhf[2][4], blf[2][4];
                uint32_t bo = b_off + ka * 16 * 272 + nh2 * 64;
                ldsm4t(bhf[0], bsh + bo);
                ldsm4t(bhf[1], bsh + bo + 32);
                ldsm4t(blf[0], bsl + bo);
                ldsm4t(blf[1], bsl + bo + 32);
#pragma unroll
                for (int j = 0; j < 2; j++)
#pragma unroll
                    for (int ma = 0; ma < 2; ma++)
#pragma unroll
                        for (int sub = 0; sub < 2; sub++)
                            mma16816(acc[ma][(nh2 * 2 + j) * 2 + sub], ahf[ma],
                                     bhf[j][sub * 2], bhf[j][sub * 2 + 1]);
#pragma unroll
                for (int j = 0; j < 2; j++)
#pragma unroll
                    for (int ma = 0; ma < 2; ma++)
#pragma unroll
                        for (int sub = 0; sub < 2; sub++)
                            mma16816(acc[ma][(nh2 * 2 + j) * 2 + sub], ahf[ma],
                                     blf[j][sub * 2], blf[j][sub * 2 + 1]);
#pragma unroll
                for (int j = 0; j < 2; j++)
#pragma unroll
                    for (int ma = 0; ma < 2; ma++)
#pragma unroll
                        for (int sub = 0; sub < 2; sub++)
                            mma16816(acc[ma][(nh2 * 2 + j) * 2 + sub], alf[ma],
                                     bhf[j][sub * 2], bhf[j][sub * 2 + 1]);
            }
        }
        __syncthreads();
    }

#pragma unroll
    for (int ma = 0; ma < 2; ma++) {
        int row = bm + wm * 32 + ma * 16 + (lane >> 2);
#pragma unroll
        for (int na = 0; na < 8; na++) {
            int col = bn + wn * 64 + na * 8 + (lane & 3) * 2;
            *(float2*)(C + (size_t)row * N + col) =
                make_float2(acc[ma][na][0], acc[ma][na][1]);
            *(float2*)(C + (size_t)(row + 8) * N + col) =
                make_float2(acc[ma][na][2], acc[ma][na][3]);
        }
    }
}

// ---------------------------------------------------------------------------
// RoPE table + apply
// ---------------------------------------------------------------------------
__global__ void rope_table_kernel() {
    int i = blockIdx.x * blockDim.x + threadIdx.x;
    if (i >= S * 64) return;
    int j = i & 63;
    int s = i >> 6;
    double ifd = exp(-((double)(2 * j) / 128.0) * log(10000.0));
    float invf = (float)ifd;
    float ang = (float)s * invf;
    double cd, sd;
    sincos((double)ang, &sd, &cd);
    g_rc[i] = (float)cd;
    g_rs[i] = (float)sd;
}

__global__ void rope_apply_kernel(float* __restrict__ x, int heads, int total) {
    int i = blockIdx.x * blockDim.x + threadIdx.x;
    if (i >= total) return;
    int j = i & 63;
    int rest = i >> 6;
    int h = rest % heads;
    int bs = rest / heads;
    int s = bs & (S - 1);
    float c = g_rc[s * 64 + j];
    float sn = g_rs[s * 64 + j];
    float* base = x + ((size_t)bs * heads + h) * HD;
    float x1 = base[j], x2 = base[j + 64];
    base[j]      = x1 * c - x2 * sn;
    base[j + 64] = x2 * c + x1 * sn;
}

// ---------------------------------------------------------------------------
// Per-chunk K mean + selection (unchanged)
// ---------------------------------------------------------------------------
__global__ void kmean_kernel() {
    int id = blockIdx.x;
    int kvh = id & 3;
    int n = (id >> 2) & 7;
    int b = id >> 5;
    int d = threadIdx.x;
    const float* base = g_K + (((size_t)b * S + n * CHUNK) * NKV + kvh) * HD + d;
    float s = 0.f;
#pragma unroll 8
    for (int i = 0; i < CHUNK; i++) s += base[(size_t)i * NKV * HD];
    g_kmean[((b * NCH + n) * NKV + kvh) * HD + d] = s * (1.0f / CHUNK);
}

__global__ void select_kernel() {
    int w = blockIdx.x * (blockDim.x >> 5) + (threadIdx.x >> 5);
    int lane = threadIdx.x & 31;
    int s = w & (S - 1);
    int h = (w >> 11) & (NH - 1);
    int b = w >> 15;
    int kvh = h >> 2;
    int qc = s >> 8;

    const float* q = g_Q + (((size_t)b * S + s) * NH + h) * HD;
    float4 qv = *(const float4*)(q + lane * 4);
    float g[8];
    for (int n = 0; n < qc; n++) {
        const float* km = g_kmean + ((b * NCH + n) * NKV + kvh) * HD;
        float4 kv = *(const float4*)(km + lane * 4);
        float p = qv.x * kv.x + qv.y * kv.y + qv.z * kv.z + qv.w * kv.w;
#pragma unroll
        for (int o = 16; o; o >>= 1) p += __shfl_xor_sync(0xffffffffu, p, o);
        g[n] = p;
    }
    if (lane == 0) {
        unsigned sel = 1u << qc;
        for (int it = 0; it < 3; it++) {
            float best = 0.f;
            int bi = -1;
            for (int n = 0; n < qc; n++)
                if (!((sel >> n) & 1) && (bi < 0 || g[n] > best)) { best = g[n]; bi = n; }
            if (bi >= 0) sel |= 1u << bi;
        }
        g_sel[w] = sel;
    }
}

// ===========================================================================
// Tensor-core sparse flash attention.
// Block = 256 threads / 8 warps, AQ=128 queries, AK=32 keys per tile.
// Warp w owns q rows [w*16, w*16+16). bf16x3 QK and PV; online softmax in
// registers; epilogue writes bf16 hi/lo O directly.
// ===========================================================================
#define AQ 128
#define AK 32
#define ASTR 136   // bf16 elems per row (272 B)

#define AT_QH 0
#define AT_QL (AQ * ASTR)
#define AT_KH (2 * AQ * ASTR)
#define AT_KL (2 * AQ * ASTR + AK * ASTR)
#define AT_VH (2 * AQ * ASTR + 2 * AK * ASTR)
#define AT_VL (2 * AQ * ASTR + 3 * AK * ASTR)
#define AT_BF16S (2 * AQ * ASTR + 4 * AK * ASTR)
#define AT_SMEM_BYTES (AT_BF16S * 2 + AQ * 4 + 16)

__global__ __launch_bounds__(256)
void attn_mma_kernel() {
    extern __shared__ __align__(16) __nv_bfloat16 smb[];
    __nv_bfloat16* sQh = smb + AT_QH;
    __nv_bfloat16* sQl = smb + AT_QL;
    __nv_bfloat16* sKh = smb + AT_KH;
    __nv_bfloat16* sKl = smb + AT_KL;
    __nv_bfloat16* sVh = smb + AT_VH;
    __nv_bfloat16* sVl = smb + AT_VL;
    unsigned* selq = (unsigned*)(smb + AT_BF16S);
    unsigned* selu_p = selq + AQ;

    int qt = gridDim.x - 1 - blockIdx.x;   // long tiles first
    int h = blockIdx.y, b = blockIdx.z;
    int kvh = h >> 2;
    int tid = threadIdx.x, lane = tid & 31, w = tid >> 5;
    int s0 = qt * AQ;
    int qc = s0 >> 8;

    // ---- stage Q (128 rows x 128 d, hi+lo) ----
    {
        int r = tid >> 1, half = tid & 1;
        size_t gq = (((size_t)b * S + s0 + r) * NH + h) * HD + half * 64;
#pragma unroll
        for (int i = 0; i < 8; i++) {
            *(uint4*)&sQh[r * ASTR + half * 64 + i * 8] = *(const uint4*)(g_Qh + gq + i * 8);
            *(uint4*)&sQl[r * ASTR + half * 64 + i * 8] = *(const uint4*)(g_Ql + gq + i * 8);
        }
    }
    if (tid == 0) *selu_p = 0;
    __syncthreads();
    if (tid < AQ) {
        unsigned sv = g_sel[((size_t)(b * NH + h) << 11) + s0 + tid];
        selq[tid] = sv;
        atomicOr(selu_p, sv);
    }
    __syncthreads();
    unsigned selu = *selu_p;

    float acc[16][4];
#pragma unroll
    for (int j = 0; j < 16; j++)
#pragma unroll
        for (int k = 0; k < 4; k++) acc[j][k] = 0.f;
    float m0 = -1e30f, m1 = -1e30f, l0 = 0.f, l1 = 0.f;

    const float scale = 0.08838834764831845f;
    int nkt = (s0 >> 5) + 4;

    uint32_t qh_b = smem_u32(sQh), ql_b = smem_u32(sQl);
    uint32_t kh_b = smem_u32(sKh), kl_b = smem_u32(sKl);
    uint32_t vh_b = smem_u32(sVh), vl_b = smem_u32(sVl);
    uint32_t a_off = (uint32_t)(w * 16 + (lane & 15)) * 272 + (lane >> 4) * 16;
    uint32_t k_off = (uint32_t)((lane & 7) + (lane >> 4) * 8) * 272 + ((lane >> 3) & 1) * 16;
    uint32_t v_off = (uint32_t)(((lane >> 3) & 1) * 8 + (lane & 7)) * 272 + (lane >> 4) * 16;

    int r0 = w * 16 + (lane >> 2);
    int r1 = r0 + 8;

    for (int kt = 0; kt < nkt; kt++) {
        int n = kt >> 3;
        bool past = (n < qc);
        if (past && !((selu >> n) & 1)) continue;

        // ---- stage K/V tile (32 x 128, hi+lo) ----
        {
            int row = tid >> 3;
            size_t gk = (((size_t)b * S + kt * AK + row) * NKV + kvh) * HD;
#pragma unroll
            for (int i = 0; i < 2; i++) {
                int g = (tid & 7) * 2 + i;
                *(uint4*)&sKh[row * ASTR + g * 8] = *(const uint4*)(g_Kh + gk + g * 8);
                *(uint4*)&sKl[row * ASTR + g * 8] = *(const uint4*)(g_Kl + gk + g * 8);
                *(uint4*)&sVh[row * ASTR + g * 8] = *(const uint4*)(g_Vh + gk + g * 8);
                *(uint4*)&sVl[row * ASTR + g * 8] = *(const uint4*)(g_Vl + gk + g * 8);
            }
        }
        __syncthreads();

        // ---- QK: scores s[4 n8 tiles][4] ----
        float s[4][4];
#pragma unroll
        for (int nt = 0; nt < 4; nt++)
#pragma unroll
            for (int k = 0; k < 4; k++) s[nt][k] = 0.f;
#pragma unroll
        for (int ka = 0; ka < 8; ka++) {
            uint32_t aqh[4], aql[4], bh0[4], bh1[4], bl0[4], bl1[4];
            ldsm4(aqh, qh_b + a_off + ka * 32);
            ldsm4(aql, ql_b + a_off + ka * 32);
            ldsm4(bh0, kh_b + k_off + ka * 32);
            ldsm4(bh1, kh_b + k_off + 16 * 272 + ka * 32);
            ldsm4(bl0, kl_b + k_off + ka * 32);
            ldsm4(bl1, kl_b + k_off + 16 * 272 + ka * 32);
            mma16816(s[0], aqh, bh0[0], bh0[1]);
            mma16816(s[1], aqh, bh0[2], bh0[3]);
            mma16816(s[2], aqh, bh1[0], bh1[1]);
            mma16816(s[3], aqh, bh1[2], bh1[3]);
            mma16816(s[0], aqh, bl0[0], bl0[1]);
            mma16816(s[1], aqh, bl0[2], bl0[3]);
            mma16816(s[2], aqh, bl1[0], bl1[1]);
            mma16816(s[3], aqh, bl1[2], bl1[3]);
            mma16816(s[0], aql, bh0[0], bh0[1]);
            mma16816(s[1], aql, bh0[2], bh0[3]);
            mma16816(s[2], aql, bh1[0], bh1[1]);
            mma16816(s[3], aql, bh1[2], bh1[3]);
        }

        // ---- mask + scale ----
        if (past) {
            bool ok0 = (selq[r0] >> n) & 1, ok1 = (selq[r1] >> n) & 1;
#pragma unroll
            for (int nt = 0; nt < 4; nt++) {
                s[nt][0] = ok0 ? s[nt][0] * scale : -3.0e38f;
                s[nt][1] = ok0 ? s[nt][1] * scale : -3.0e38f;
                s[nt][2] = ok1 ? s[nt][2] * scale : -3.0e38f;
                s[nt][3] = ok1 ? s[nt][3] * scale : -3.0e38f;
            }
        } else {
            int q0 = s0 + r0, q1 = s0 + r1;
#pragma unroll
            for (int nt = 0; nt < 4; nt++) {
                int t = kt * 32 + nt * 8 + (lane & 3) * 2;
                s[nt][0] = (t     <= q0) ? s[nt][0] * scale : -3.0e38f;
                s[nt][1] = (t + 1 <= q0) ? s[nt][1] * scale : -3.0e38f;
                s[nt][2] = (t     <= q1) ? s[nt][2] * scale : -3.0e38f;
                s[nt][3] = (t + 1 <= q1) ? s[nt][3] * scale : -3.0e38f;
            }
        }

        // ---- online softmax ----
        float mx0 = -3.0e38f, mx1 = -3.0e38f;
#pragma unroll
        for (int nt = 0; nt < 4; nt++) {
            mx0 = fmaxf(mx0, fmaxf(s[nt][0], s[nt][1]));
            mx1 = fmaxf(mx1, fmaxf(s[nt][2], s[nt][3]));
        }
        mx0 = fmaxf(mx0, __shfl_xor_sync(0xffffffffu, mx0, 1));
        mx0 = fmaxf(mx0, __shfl_xor_sync(0xffffffffu, mx0, 2));
        mx1 = fmaxf(mx1, __shfl_xor_sync(0xffffffffu, mx1, 1));
        mx1 = fmaxf(mx1, __shfl_xor_sync(0xffffffffu, mx1, 2));
        float mn0 = fmaxf(m0, mx0), mn1 = fmaxf(m1, mx1);
        float f0 = __expf(m0 - mn0), f1 = __expf(m1 - mn1);

        float sum0 = 0.f, sum1 = 0.f;
        uint32_t ph[4][2], pl[4][2];
#pragma unroll
        for (int nt = 0; nt < 4; nt++) {
            float p0 = __expf(s[nt][0] - mn0);
            float p1 = __expf(s[nt][1] - mn0);
            float p2 = __expf(s[nt][2] - mn1);
            float p3 = __expf(s[nt][3] - mn1);
            sum0 += p0 + p1;
            sum1 += p2 + p3;
            __nv_bfloat16 h0, h1, h2, h3, q0b, q1b, q2b, q3b;
            split1(p0, h0, q0b);
            split1(p1, h1, q1b);
            split1(p2, h2, q2b);
            split1(p3, h3, q3b);
            ph[nt][0] = packbf(h0, h1);
            ph[nt][1] = packbf(h2, h3);
            pl[nt][0] = packbf(q0b, q1b);
            pl[nt][1] = packbf(q2b, q3b);
        }
        sum0 += __shfl_xor_sync(0xffffffffu, sum0, 1);
        sum0 += __shfl_xor_sync(0xffffffffu, sum0, 2);
        sum1 += __shfl_xor_sync(0xffffffffu, sum1, 1);
        sum1 += __shfl_xor_sync(0xffffffffu, sum1, 2);
        l0 = l0 * f0 + sum0;
        l1 = l1 * f1 + sum1;
        m0 = mn0;
        m1 = mn1;
#pragma unroll
        for (int j = 0; j < 16; j++) {
            acc[j][0] *= f0;
            acc[j][1] *= f0;
            acc[j][2] *= f1;
            acc[j][3] *= f1;
        }

        // ---- PV: acc[d tile][.] += P * V ----
#pragma unroll
        for (int kg = 0; kg < 2; kg++) {
            uint32_t aPh[4] = {ph[kg * 2][0], ph[kg * 2][1], ph[kg * 2 + 1][0], ph[kg * 2 + 1][1]};
            uint32_t aPl[4] = {pl[kg * 2][0], pl[kg * 2][1], pl[kg * 2 + 1][0], pl[kg * 2 + 1][1]};
#pragma unroll
            for (int dn = 0; dn < 8; dn++) {
                uint32_t bvh[4], bvl[4];
                ldsm4t(bvh, vh_b + v_off + kg * 16 * 272 + dn * 32);
                ldsm4t(bvl, vl_b + v_off + kg * 16 * 272 + dn * 32);
                mma16816(acc[dn * 2],     aPh, bvh[0], bvh[1]);
                mma16816(acc[dn * 2 + 1], aPh, bvh[2], bvh[3]);
                mma16816(acc[dn * 2],     aPh, bvl[0], bvl[1]);
                mma16816(acc[dn * 2 + 1], aPh, bvl[2], bvl[3]);
                mma16816(acc[dn * 2],     aPl, bvh[0], bvh[1]);
                mma16816(acc[dn * 2 + 1], aPl, bvh[2], bvh[3]);
            }
        }
        __syncthreads();
    }

    // ---- epilogue: normalize, split to bf16 hi/lo, store ----
    float inv0 = 1.0f / l0, inv1 = 1.0f / l1;
    size_t ob0 = (((size_t)b * S + s0 + r0) * NH + h) * HD;
    size_t ob1 = (((size_t)b * S + s0 + r1) * NH + h) * HD;
#pragma unroll
    for (int j = 0; j < 16; j++) {
        int d = j * 8 + (lane & 3) * 2;
        float o0 = acc[j][0] * inv0, o1 = acc[j][1] * inv0;
        float o2 = acc[j][2] * inv1, o3 = acc[j][3] * inv1;
        __nv_bfloat16 h0, h1, h2, h3, q0b, q1b, q2b, q3b;
        split1(o0, h0, q0b);
        split1(o1, h1, q1b);
        split1(o2, h2, q2b);
        split1(o3, h3, q3b);
        *(uint32_t*)(g_oh + ob0 + d) = packbf(h0, h1);
        *(uint32_t*)(g_ol + ob0 + d) = packbf(q0b, q1b);
        *(uint32_t*)(g_oh + ob1 + d) = packbf(h2, h3);
        *(uint32_t*)(g_ol + ob1 + d) = packbf(q2b, q3b);
    }
}

// ---------------------------------------------------------------------------
extern "C" void kernel_launch(void* const* d_in, const int* in_sizes, int n_in,
                              void* d_out, int out_size) {
    const float* x  = (const float*)d_in[0];
    const float* wq = (const float*)d_in[1];
    const float* wk = (const float*)d_in[2];
    const float* wv = (const float*)d_in[3];
    const float* wo = (const float*)d_in[4];
    float* out = (float*)d_out;

    float *Q, *K, *V;
    cudaGetSymbolAddress((void**)&Q, g_Q);
    cudaGetSymbolAddress((void**)&K, g_K);
    cudaGetSymbolAddress((void**)&V, g_V);

    __nv_bfloat16 *xh, *xl, *wqh, *wql, *wkh, *wkl, *wvh, *wvl, *woh, *wol, *oh, *ol;
    __nv_bfloat16 *Qh, *Ql, *Kh, *Kl, *Vh, *Vl;
    cudaGetSymbolAddress((void**)&xh, g_xh);
    cudaGetSymbolAddress((void**)&xl, g_xl);
    cudaGetSymbolAddress((void**)&wqh, g_wqh);
    cudaGetSymbolAddress((void**)&wql, g_wql);
    cudaGetSymbolAddress((void**)&wkh, g_wkh);
    cudaGetSymbolAddress((void**)&wkl, g_wkl);
    cudaGetSymbolAddress((void**)&wvh, g_wvh);
    cudaGetSymbolAddress((void**)&wvl, g_wvl);
    cudaGetSymbolAddress((void**)&woh, g_woh);
    cudaGetSymbolAddress((void**)&wol, g_wol);
    cudaGetSymbolAddress((void**)&oh, g_oh);
    cudaGetSymbolAddress((void**)&ol, g_ol);
    cudaGetSymbolAddress((void**)&Qh, g_Qh);
    cudaGetSymbolAddress((void**)&Ql, g_Ql);
    cudaGetSymbolAddress((void**)&Kh, g_Kh);
    cudaGetSymbolAddress((void**)&Kl, g_Kl);
    cudaGetSymbolAddress((void**)&Vh, g_Vh);
    cudaGetSymbolAddress((void**)&Vl, g_Vl);

    const int M = B * S;  // 4096
    cudaFuncSetAttribute(attn_mma_kernel,
                         cudaFuncAttributeMaxDynamicSharedMemorySize, AT_SMEM_BYTES);

    rope_table_kernel<<<(S * 64 + 255) / 256, 256>>>();

    // pre-split inputs/weights
    {
        int n4;
        n4 = (M * HID) / 4;
        split_kernel<<<(n4 + 255) / 256, 256>>>(x, xh, xl, n4);
        n4 = (HID * NH * HD) / 4;
        split_kernel<<<(n4 + 255) / 256, 256>>>(wq, wqh, wql, n4);
        n4 = (HID * NKV * HD) / 4;
        split_kernel<<<(n4 + 255) / 256, 256>>>(wk, wkh, wkl, n4);
        split_kernel<<<(n4 + 255) / 256, 256>>>(wv, wvh, wvl, n4);
        n4 = (NH * HD * HID) / 4;
        split_kernel<<<(n4 + 255) / 256, 256>>>(wo, woh, wol, n4);
    }

    // projections
    gemm_mma<<<dim3((NH * HD) / GBN, M / GBM), 256>>>(xh, xl, wqh, wql, Q, M, NH * HD, HID);
    gemm_mma<<<dim3((NKV * HD) / GBN, M / GBM), 256>>>(xh, xl, wkh, wkl, K, M, NKV * HD, HID);
    gemm_mma<<<dim3((NKV * HD) / GBN, M / GBM), 256>>>(xh, xl, wvh, wvl, V, M, NKV * HD, HID);

    // RoPE
    {
        int totq = B * S * NH * 64;
        rope_apply_kernel<<<(totq + 255) / 256, 256>>>(Q, NH, totq);
        int totk = B * S * NKV * 64;
        rope_apply_kernel<<<(totk + 255) / 256, 256>>>(K, NKV, totk);
    }

    // split post-RoPE Q/K and V for tensor-core attention
    {
        int n4 = (B * S * NH * HD) / 4;
        split_kernel<<<(n4 + 255) / 256, 256>>>(Q, Qh, Ql, n4);
        n4 = (B * S * NKV * HD) / 4;
        split_kernel<<<(n4 + 255) / 256, 256>>>(K, Kh, Kl, n4);
        split_kernel<<<(n4 + 255) / 256, 256>>>(V, Vh, Vl, n4);
    }

    // chunk means + selection
    kmean_kernel<<<B * NCH * NKV, 128>>>();
    select_kernel<<<(B * NH * S) / 8, 256>>>();

    // tensor-core sparse attention (writes g_oh/g_ol directly)
    attn_mma_kernel<<<dim3(S / AQ, NH, B), 256, AT_SMEM_BYTES>>>();

    // output projection
    gemm_mma<<<dim3(HID / GBN, M / GBM), 256>>>(oh, ol, woh, wol, out, M, HID, HID);
}

// round 7
// speedup vs baseline: 4.9023x; 1.0716x over previous
#include <cuda_runtime.h>
#include <cuda_bf16.h>
#include <math.h>
#include <stdint.h>

// Problem constants
#define B 2
#define S 2048
#define HID 2048
#define NH 16
#define NKV 4
#define HD 128
#define CHUNK 256
#define NCH 8

// Scratch (static device allocations; no cudaMalloc allowed)
__device__ float g_Q[(size_t)B * S * NH * HD];
__device__ float g_K[(size_t)B * S * NKV * HD];
__device__ float g_V[(size_t)B * S * NKV * HD];
__device__ float g_kmean[(size_t)B * NCH * NKV * HD];
__device__ unsigned g_sel[(size_t)B * NH * S];
__device__ float g_rc[(size_t)S * 64];
__device__ float g_rs[(size_t)S * 64];

// bf16 hi/lo split copies
__device__ __nv_bfloat16 g_xh[(size_t)B * S * HID];
__device__ __nv_bfloat16 g_xl[(size_t)B * S * HID];
__device__ __nv_bfloat16 g_wqh[(size_t)HID * NH * HD];
__device__ __nv_bfloat16 g_wql[(size_t)HID * NH * HD];
__device__ __nv_bfloat16 g_wkh[(size_t)HID * NKV * HD];
__device__ __nv_bfloat16 g_wkl[(size_t)HID * NKV * HD];
__device__ __nv_bfloat16 g_wvh[(size_t)HID * NKV * HD];
__device__ __nv_bfloat16 g_wvl[(size_t)HID * NKV * HD];
__device__ __nv_bfloat16 g_woh[(size_t)NH * HD * HID];
__device__ __nv_bfloat16 g_wol[(size_t)NH * HD * HID];
__device__ __nv_bfloat16 g_oh[(size_t)B * S * NH * HD];
__device__ __nv_bfloat16 g_ol[(size_t)B * S * NH * HD];
// post-RoPE bf16 splits for attention
__device__ __nv_bfloat16 g_Qh[(size_t)B * S * NH * HD];
__device__ __nv_bfloat16 g_Ql[(size_t)B * S * NH * HD];
__device__ __nv_bfloat16 g_Kh[(size_t)B * S * NKV * HD];
__device__ __nv_bfloat16 g_Kl[(size_t)B * S * NKV * HD];
__device__ __nv_bfloat16 g_Vh[(size_t)B * S * NKV * HD];
__device__ __nv_bfloat16 g_Vl[(size_t)B * S * NKV * HD];

// ===========================================================================
// helpers
// ===========================================================================
__device__ __forceinline__ uint32_t smem_u32(const void* p) {
    uint32_t a;
    asm("{ .reg .u64 t; cvta.to.shared.u64 t, %1; cvt.u32.u64 %0, t; }"
        : "=r"(a) : "l"(p));
    return a;
}

__device__ __forceinline__ void ldsm4(uint32_t* r, uint32_t addr) {
    asm volatile("ldmatrix.sync.aligned.m8n8.x4.shared.b16 {%0,%1,%2,%3}, [%4];"
                 : "=r"(r[0]), "=r"(r[1]), "=r"(r[2]), "=r"(r[3]) : "r"(addr));
}
__device__ __forceinline__ void ldsm4t(uint32_t* r, uint32_t addr) {
    asm volatile("ldmatrix.sync.aligned.m8n8.x4.trans.shared.b16 {%0,%1,%2,%3}, [%4];"
                 : "=r"(r[0]), "=r"(r[1]), "=r"(r[2]), "=r"(r[3]) : "r"(addr));
}
__device__ __forceinline__ void mma16816(float* c, const uint32_t* a,
                                         uint32_t b0, uint32_t b1) {
    asm volatile(
        "mma.sync.aligned.m16n8k16.row.col.f32.bf16.bf16.f32 "
        "{%0,%1,%2,%3}, {%4,%5,%6,%7}, {%8,%9}, {%0,%1,%2,%3};"
        : "+f"(c[0]), "+f"(c[1]), "+f"(c[2]), "+f"(c[3])
        : "r"(a[0]), "r"(a[1]), "r"(a[2]), "r"(a[3]), "r"(b0), "r"(b1));
}
__device__ __forceinline__ void cpa16(uint32_t s, const void* g) {
    asm volatile("cp.async.cg.shared.global [%0], [%1], 16;" :: "r"(s), "l"(g));
}

__device__ __forceinline__ void split1(float a, __nv_bfloat16& h, __nv_bfloat16& l) {
    h = __float2bfloat16_rn(a);
    l = __float2bfloat16_rn(a - __bfloat162float(h));
}
__device__ __forceinline__ uint32_t packbf(__nv_bfloat16 lo, __nv_bfloat16 hi) {
    return ((uint32_t)__bfloat16_as_ushort(hi) << 16) | __bfloat16_as_ushort(lo);
}

// ---------------------------------------------------------------------------
// split kernel: fp32 -> bf16 hi + lo
// ---------------------------------------------------------------------------
__global__ void split_kernel(const float* __restrict__ in,
                             __nv_bfloat16* __restrict__ hi,
                             __nv_bfloat16* __restrict__ lo, int n4) {
    int i = blockIdx.x * blockDim.x + threadIdx.x;
    if (i >= n4) return;
    float4 v = ((const float4*)in)[i];
    __nv_bfloat16 h0, h1, h2, h3, l0, l1, l2, l3;
    split1(v.x, h0, l0);
    split1(v.y, h1, l1);
    split1(v.z, h2, l2);
    split1(v.w, h3, l3);
    ((uint2*)hi)[i] = make_uint2(packbf(h0, h1), packbf(h2, h3));
    ((uint2*)lo)[i] = make_uint2(packbf(l0, l1), packbf(l2, l3));
}

// ===========================================================================
// bf16x3 GEMM, cp.async 2-stage pipelined.
// Block 128x128xBK32, 256 threads, 8 warps (4Mx2N), warp tile 32x64.
// Dynamic smem: 2 stages x {Ah,Al:128x40, Bh,Bl:32x136} bf16 = 75776 B.
// ===========================================================================
#define GBK 32
#define PAH 0
#define PAL 10240
#define PBH 20480
#define PBL 29184
#define PSTAGE 37888
#define GEMM_SMEM (2 * PSTAGE)

__device__ __forceinline__ void gemm_issue(
    uint32_t st, const __nv_bfloat16* Ah, const __nv_bfloat16* Al,
    const __nv_bfloat16* Bh, const __nv_bfloat16* Bl,
    int bm, int bn, int k0, int N, int K, int tid) {
#pragma unroll
    for (int i = 0; i < 2; i++) {
        int c = tid + i * 256;
        int row = c >> 2, q = c & 3;
        size_t g = (size_t)(bm + row) * K + k0 + q * 8;
        cpa16(st + PAH + row * 80 + q * 16, Ah + g);
        cpa16(st + PAL + row * 80 + q * 16, Al + g);
    }
#pragma unroll
    for (int i = 0; i < 2; i++) {
        int c = tid + i * 256;
        int row = c >> 4, q = c & 15;
        size_t g = (size_t)(k0 + row) * N + bn + q * 8;
        cpa16(st + PBH + row * 272 + q * 16, Bh + g);
        cpa16(st + PBL + row * 272 + q * 16, Bl + g);
    }
    asm volatile("cp.async.commit_group;");
}

__device__ __forceinline__ void gemm_body(
    const __nv_bfloat16* __restrict__ Ah, const __nv_bfloat16* __restrict__ Al,
    const __nv_bfloat16* __restrict__ Bh, const __nv_bfloat16* __restrict__ Bl,
    float* __restrict__ C, int N, int K, int bm, int bn, char* smem) {
    int tid = threadIdx.x;
    int lane = tid & 31, wid = tid >> 5;
    int wm = wid & 3, wn = wid >> 2;

    float acc[2][8][4];
#pragma unroll
    for (int i = 0; i < 2; i++)
#pragma unroll
        for (int j = 0; j < 8; j++)
#pragma unroll
            for (int k = 0; k < 4; k++) acc[i][j][k] = 0.f;

    uint32_t sb = smem_u32(smem);
    int l15 = lane & 15, l16 = lane >> 4;
    uint32_t a_off = (uint32_t)(wm * 32 + l15) * 80 + l16 * 16;
    uint32_t b_off = (uint32_t)(((lane >> 3) & 1) * 8 + (lane & 7)) * 272
                   + wn * 128 + l16 * 16;

    int niter = K / GBK;
    gemm_issue(sb, Ah, Al, Bh, Bl, bm, bn, 0, N, K, tid);

    for (int it = 0; it < niter; it++) {
        if (it + 1 < niter) {
            gemm_issue(sb + ((it + 1) & 1) * PSTAGE, Ah, Al, Bh, Bl,
                       bm, bn, (it + 1) * GBK, N, K, tid);
            asm volatile("cp.async.wait_group 1;");
        } else {
            asm volatile("cp.async.wait_group 0;");
        }
        __syncthreads();

        uint32_t st = sb + (it & 1) * PSTAGE;
        uint32_t ash = st + PAH, asl = st + PAL;
        uint32_t bsh = st + PBH, bsl = st + PBL;
#pragma unroll
        for (int ka = 0; ka < 2; ka++) {
            uint32_t ahf[2][4], alf[2][4];
            ldsm4(ahf[0], ash + a_off + ka * 32);
            ldsm4(ahf[1], ash + a_off + ka * 32 + 16 * 80);
            ldsm4(alf[0], asl + a_off + ka * 32);
            ldsm4(alf[1], asl + a_off + ka * 32 + 16 * 80);
#pragma unroll
            for (int nh2 = 0; nh2 < 2; nh2++) {
                uint32_t bhf[2][4], blf[2][4];
                uint32_t bo = b_off + ka * 16 * 272 + nh2 * 64;
                ldsm4t(bhf[0], bsh + bo);
                ldsm4t(bhf[1], bsh + bo + 32);
                ldsm4t(blf[0], bsl + bo);
                ldsm4t(blf[1], bsl + bo + 32);
#pragma unroll
                for (int j = 0; j < 2; j++)
#pragma unroll
                    for (int ma = 0; ma < 2; ma++)
#pragma unroll
                        for (int sub = 0; sub < 2; sub++)
                            mma16816(acc[ma][(nh2 * 2 + j) * 2 + sub], ahf[ma],
                                     bhf[j][sub * 2], bhf[j][sub * 2 + 1]);
#pragma unroll
                for (int j = 0; j < 2; j++)
#pragma unroll
                    for (int ma = 0; ma < 2; ma++)
#pragma unroll
                        for (int sub = 0; sub < 2; sub++)
                            mma16816(acc[ma][(nh2 * 2 + j) * 2 + sub], ahf[ma],
                                     blf[j][sub * 2], blf[j][sub * 2 + 1]);
#pragma unroll
                for (int j = 0; j < 2; j++)
#pragma unroll
                    for (int ma = 0; ma < 2; ma++)
#pragma unroll
                        for (int sub = 0; sub < 2; sub++)
                            mma16816(acc[ma][(nh2 * 2 + j) * 2 + sub], alf[ma],
                                     bhf[j][sub * 2], bhf[j][sub * 2 + 1]);
            }
        }
        __syncthreads();
    }

#pragma unroll
    for (int ma = 0; ma < 2; ma++) {
        int row = bm + wm * 32 + ma * 16 + (lane >> 2);
#pragma unroll
        for (int na = 0; na < 8; na++) {
            int col = bn + wn * 64 + na * 8 + (lane & 3) * 2;
            *(float2*)(C + (size_t)row * N + col) =
                make_float2(acc[ma][na][0], acc[ma][na][1]);
            *(float2*)(C + (size_t)(row + 8) * N + col) =
                make_float2(acc[ma][na][2], acc[ma][na][3]);
        }
    }
}

// Fused Q/K/V projection: grid (24, 32). bx<16 -> Q (N=2048); 16..19 -> K;
// 20..23 -> V (N=512 each).
__global__ __launch_bounds__(256, 2)
void gemm_qkv_kernel() {
    extern __shared__ char smem[];
    int bx = blockIdx.x;
    const __nv_bfloat16 *Bh, *Bl;
    float* C;
    int N, bn;
    if (bx < 16) {
        Bh = g_wqh; Bl = g_wql; C = g_Q; N = NH * HD; bn = bx * 128;
    } else if (bx < 20) {
        Bh = g_wkh; Bl = g_wkl; C = g_K; N = NKV * HD; bn = (bx - 16) * 128;
    } else {
        Bh = g_wvh; Bl = g_wvl; C = g_V; N = NKV * HD; bn = (bx - 20) * 128;
    }
    gemm_body(g_xh, g_xl, Bh, Bl, C, N, HID, blockIdx.y * 128, bn, smem);
}

// Output projection: grid (16, 32).
__global__ __launch_bounds__(256, 2)
void gemm_out_kernel(float* __restrict__ C) {
    extern __shared__ char smem[];
    gemm_body(g_oh, g_ol, g_woh, g_wol, C, HID, NH * HD,
              blockIdx.y * 128, blockIdx.x * 128, smem);
}

// ---------------------------------------------------------------------------
// RoPE table + apply
// ---------------------------------------------------------------------------
__global__ void rope_table_kernel() {
    int i = blockIdx.x * blockDim.x + threadIdx.x;
    if (i >= S * 64) return;
    int j = i & 63;
    int s = i >> 6;
    double ifd = exp(-((double)(2 * j) / 128.0) * log(10000.0));
    float invf = (float)ifd;
    float ang = (float)s * invf;
    double cd, sd;
    sincos((double)ang, &sd, &cd);
    g_rc[i] = (float)cd;
    g_rs[i] = (float)sd;
}

__global__ void rope_apply_kernel(float* __restrict__ x, int heads, int total) {
    int i = blockIdx.x * blockDim.x + threadIdx.x;
    if (i >= total) return;
    int j = i & 63;
    int rest = i >> 6;
    int h = rest % heads;
    int bs = rest / heads;
    int s = bs & (S - 1);
    float c = g_rc[s * 64 + j];
    float sn = g_rs[s * 64 + j];
    float* base = x + ((size_t)bs * heads + h) * HD;
    float x1 = base[j], x2 = base[j + 64];
    base[j]      = x1 * c - x2 * sn;
    base[j + 64] = x2 * c + x1 * sn;
}

// ---------------------------------------------------------------------------
// Per-chunk K mean + selection
// ---------------------------------------------------------------------------
__global__ void kmean_kernel() {
    int id = blockIdx.x;
    int kvh = id & 3;
    int n = (id >> 2) & 7;
    int b = id >> 5;
    int d = threadIdx.x;
    const float* base = g_K + (((size_t)b * S + n * CHUNK) * NKV + kvh) * HD + d;
    float s = 0.f;
#pragma unroll 8
    for (int i = 0; i < CHUNK; i++) s += base[(size_t)i * NKV * HD];
    g_kmean[((b * NCH + n) * NKV + kvh) * HD + d] = s * (1.0f / CHUNK);
}

__global__ void select_kernel() {
    int w = blockIdx.x * (blockDim.x >> 5) + (threadIdx.x >> 5);
    int lane = threadIdx.x & 31;
    int s = w & (S - 1);
    int h = (w >> 11) & (NH - 1);
    int b = w >> 15;
    int kvh = h >> 2;
    int qc = s >> 8;

    const float* q = g_Q + (((size_t)b * S + s) * NH + h) * HD;
    float4 qv = *(const float4*)(q + lane * 4);
    float g[8];
    for (int n = 0; n < qc; n++) {
        const float* km = g_kmean + ((b * NCH + n) * NKV + kvh) * HD;
        float4 kv = *(const float4*)(km + lane * 4);
        float p = qv.x * kv.x + qv.y * kv.y + qv.z * kv.z + qv.w * kv.w;
#pragma unroll
        for (int o = 16; o; o >>= 1) p += __shfl_xor_sync(0xffffffffu, p, o);
        g[n] = p;
    }
    if (lane == 0) {
        unsigned sel = 1u << qc;
        for (int it = 0; it < 3; it++) {
            float best = 0.f;
            int bi = -1;
            for (int n = 0; n < qc; n++)
                if (!((sel >> n) & 1) && (bi < 0 || g[n] > best)) { best = g[n]; bi = n; }
            if (bi >= 0) sel |= 1u << bi;
        }
        g_sel[w] = sel;
    }
}

// ===========================================================================
// Tensor-core sparse flash attention (unchanged from R6)
// ===========================================================================
#define AQ 128
#define AK 32
#define ASTR 136

#define AT_QH 0
#define AT_QL (AQ * ASTR)
#define AT_KH (2 * AQ * ASTR)
#define AT_KL (2 * AQ * ASTR + AK * ASTR)
#define AT_VH (2 * AQ * ASTR + 2 * AK * ASTR)
#define AT_VL (2 * AQ * ASTR + 3 * AK * ASTR)
#define AT_BF16S (2 * AQ * ASTR + 4 * AK * ASTR)
#define AT_SMEM_BYTES (AT_BF16S * 2 + AQ * 4 + 16)

__global__ __launch_bounds__(256)
void attn_mma_kernel() {
    extern __shared__ __align__(16) __nv_bfloat16 smb[];
    __nv_bfloat16* sQh = smb + AT_QH;
    __nv_bfloat16* sQl = smb + AT_QL;
    __nv_bfloat16* sKh = smb + AT_KH;
    __nv_bfloat16* sKl = smb + AT_KL;
    __nv_bfloat16* sVh = smb + AT_VH;
    __nv_bfloat16* sVl = smb + AT_VL;
    unsigned* selq = (unsigned*)(smb + AT_BF16S);
    unsigned* selu_p = selq + AQ;

    int qt = gridDim.x - 1 - blockIdx.x;
    int h = blockIdx.y, b = blockIdx.z;
    int kvh = h >> 2;
    int tid = threadIdx.x, lane = tid & 31, w = tid >> 5;
    int s0 = qt * AQ;
    int qc = s0 >> 8;

    {
        int r = tid >> 1, half = tid & 1;
        size_t gq = (((size_t)b * S + s0 + r) * NH + h) * HD + half * 64;
#pragma unroll
        for (int i = 0; i < 8; i++) {
            *(uint4*)&sQh[r * ASTR + half * 64 + i * 8] = *(const uint4*)(g_Qh + gq + i * 8);
            *(uint4*)&sQl[r * ASTR + half * 64 + i * 8] = *(const uint4*)(g_Ql + gq + i * 8);
        }
    }
    if (tid == 0) *selu_p = 0;
    __syncthreads();
    if (tid < AQ) {
        unsigned sv = g_sel[((size_t)(b * NH + h) << 11) + s0 + tid];
        selq[tid] = sv;
        atomicOr(selu_p, sv);
    }
    __syncthreads();
    unsigned selu = *selu_p;

    float acc[16][4];
#pragma unroll
    for (int j = 0; j < 16; j++)
#pragma unroll
        for (int k = 0; k < 4; k++) acc[j][k] = 0.f;
    float m0 = -1e30f, m1 = -1e30f, l0 = 0.f, l1 = 0.f;

    const float scale = 0.08838834764831845f;
    int nkt = (s0 >> 5) + 4;

    uint32_t qh_b = smem_u32(sQh), ql_b = smem_u32(sQl);
    uint32_t kh_b = smem_u32(sKh), kl_b = smem_u32(sKl);
    uint32_t vh_b = smem_u32(sVh), vl_b = smem_u32(sVl);
    uint32_t a_off = (uint32_t)(w * 16 + (lane & 15)) * 272 + (lane >> 4) * 16;
    uint32_t k_off = (uint32_t)((lane & 7) + (lane >> 4) * 8) * 272 + ((lane >> 3) & 1) * 16;
    uint32_t v_off = (uint32_t)(((lane >> 3) & 1) * 8 + (lane & 7)) * 272 + (lane >> 4) * 16;

    int r0 = w * 16 + (lane >> 2);
    int r1 = r0 + 8;

    for (int kt = 0; kt < nkt; kt++) {
        int n = kt >> 3;
        bool past = (n < qc);
        if (past && !((selu >> n) & 1)) continue;

        {
            int row = tid >> 3;
            size_t gk = (((size_t)b * S + kt * AK + row) * NKV + kvh) * HD;
#pragma unroll
            for (int i = 0; i < 2; i++) {
                int g = (tid & 7) * 2 + i;
                *(uint4*)&sKh[row * ASTR + g * 8] = *(const uint4*)(g_Kh + gk + g * 8);
                *(uint4*)&sKl[row * ASTR + g * 8] = *(const uint4*)(g_Kl + gk + g * 8);
                *(uint4*)&sVh[row * ASTR + g * 8] = *(const uint4*)(g_Vh + gk + g * 8);
                *(uint4*)&sVl[row * ASTR + g * 8] = *(const uint4*)(g_Vl + gk + g * 8);
            }
        }
        __syncthreads();

        float s[4][4];
#pragma unroll
        for (int nt = 0; nt < 4; nt++)
#pragma unroll
            for (int k = 0; k < 4; k++) s[nt][k] = 0.f;
#pragma unroll
        for (int ka = 0; ka < 8; ka++) {
            uint32_t aqh[4], aql[4], bh0[4], bh1[4], bl0[4], bl1[4];
            ldsm4(aqh, qh_b + a_off + ka * 32);
            ldsm4(aql, ql_b + a_off + ka * 32);
            ldsm4(bh0, kh_b + k_off + ka * 32);
            ldsm4(bh1, kh_b + k_off + 16 * 272 + ka * 32);
            ldsm4(bl0, kl_b + k_off + ka * 32);
            ldsm4(bl1, kl_b + k_off + 16 * 272 + ka * 32);
            mma16816(s[0], aqh, bh0[0], bh0[1]);
            mma16816(s[1], aqh, bh0[2], bh0[3]);
            mma16816(s[2], aqh, bh1[0], bh1[1]);
            mma16816(s[3], aqh, bh1[2], bh1[3]);
            mma16816(s[0], aqh, bl0[0], bl0[1]);
            mma16816(s[1], aqh, bl0[2], bl0[3]);
            mma16816(s[2], aqh, bl1[0], bl1[1]);
            mma16816(s[3], aqh, bl1[2], bl1[3]);
            mma16816(s[0], aql, bh0[0], bh0[1]);
            mma16816(s[1], aql, bh0[2], bh0[3]);
            mma16816(s[2], aql, bh1[0], bh1[1]);
            mma16816(s[3], aql, bh1[2], bh1[3]);
        }

        if (past) {
            bool ok0 = (selq[r0] >> n) & 1, ok1 = (selq[r1] >> n) & 1;
#pragma unroll
            for (int nt = 0; nt < 4; nt++) {
                s[nt][0] = ok0 ? s[nt][0] * scale : -3.0e38f;
                s[nt][1] = ok0 ? s[nt][1] * scale : -3.0e38f;
                s[nt][2] = ok1 ? s[nt][2] * scale : -3.0e38f;
                s[nt][3] = ok1 ? s[nt][3] * scale : -3.0e38f;
            }
        } else {
            int q0 = s0 + r0, q1 = s0 + r1;
#pragma unroll
            for (int nt = 0; nt < 4; nt++) {
                int t = kt * 32 + nt * 8 + (lane & 3) * 2;
                s[nt][0] = (t     <= q0) ? s[nt][0] * scale : -3.0e38f;
                s[nt][1] = (t + 1 <= q0) ? s[nt][1] * scale : -3.0e38f;
                s[nt][2] = (t     <= q1) ? s[nt][2] * scale : -3.0e38f;
                s[nt][3] = (t + 1 <= q1) ? s[nt][3] * scale : -3.0e38f;
            }
        }

        float mx0 = -3.0e38f, mx1 = -3.0e38f;
#pragma unroll
        for (int nt = 0; nt < 4; nt++) {
            mx0 = fmaxf(mx0, fmaxf(s[nt][0], s[nt][1]));
            mx1 = fmaxf(mx1, fmaxf(s[nt][2], s[nt][3]));
        }
        mx0 = fmaxf(mx0, __shfl_xor_sync(0xffffffffu, mx0, 1));
        mx0 = fmaxf(mx0, __shfl_xor_sync(0xffffffffu, mx0, 2));
        mx1 = fmaxf(mx1, __shfl_xor_sync(0xffffffffu, mx1, 1));
        mx1 = fmaxf(mx1, __shfl_xor_sync(0xffffffffu, mx1, 2));
        float mn0 = fmaxf(m0, mx0), mn1 = fmaxf(m1, mx1);
        float f0 = __expf(m0 - mn0), f1 = __expf(m1 - mn1);

        float sum0 = 0.f, sum1 = 0.f;
        uint32_t ph[4][2], pl[4][2];
#pragma unroll
        for (int nt = 0; nt < 4; nt++) {
            float p0 = __expf(s[nt][0] - mn0);
            float p1 = __expf(s[nt][1] - mn0);
            float p2 = __expf(s[nt][2] - mn1);
            float p3 = __expf(s[nt][3] - mn1);
            sum0 += p0 + p1;
            sum1 += p2 + p3;
            __nv_bfloat16 h0, h1, h2, h3, q0b, q1b, q2b, q3b;
            split1(p0, h0, q0b);
            split1(p1, h1, q1b);
            split1(p2, h2, q2b);
            split1(p3, h3, q3b);
            ph[nt][0] = packbf(h0, h1);
            ph[nt][1] = packbf(h2, h3);
            pl[nt][0] = packbf(q0b, q1b);
            pl[nt][1] = packbf(q2b, q3b);
        }
        sum0 += __shfl_xor_sync(0xffffffffu, sum0, 1);
        sum0 += __shfl_xor_sync(0xffffffffu, sum0, 2);
        sum1 += __shfl_xor_sync(0xffffffffu, sum1, 1);
        sum1 += __shfl_xor_sync(0xffffffffu, sum1, 2);
        l0 = l0 * f0 + sum0;
        l1 = l1 * f1 + sum1;
        m0 = mn0;
        m1 = mn1;
#pragma unroll
        for (int j = 0; j < 16; j++) {
            acc[j][0] *= f0;
            acc[j][1] *= f0;
            acc[j][2] *= f1;
            acc[j][3] *= f1;
        }

#pragma unroll
        for (int kg = 0; kg < 2; kg++) {
            uint32_t aPh[4] = {ph[kg * 2][0], ph[kg * 2][1], ph[kg * 2 + 1][0], ph[kg * 2 + 1][1]};
            uint32_t aPl[4] = {pl[kg * 2][0], pl[kg * 2][1], pl[kg * 2 + 1][0], pl[kg * 2 + 1][1]};
#pragma unroll
            for (int dn = 0; dn < 8; dn++) {
                uint32_t bvh[4], bvl[4];
                ldsm4t(bvh, vh_b + v_off + kg * 16 * 272 + dn * 32);
                ldsm4t(bvl, vl_b + v_off + kg * 16 * 272 + dn * 32);
                mma16816(acc[dn * 2],     aPh, bvh[0], bvh[1]);
                mma16816(acc[dn * 2 + 1], aPh, bvh[2], bvh[3]);
                mma16816(acc[dn * 2],     aPh, bvl[0], bvl[1]);
                mma16816(acc[dn * 2 + 1], aPh, bvl[2], bvl[3]);
                mma16816(acc[dn * 2],     aPl, bvh[0], bvh[1]);
                mma16816(acc[dn * 2 + 1], aPl, bvh[2], bvh[3]);
            }
        }
        __syncthreads();
    }

    float inv0 = 1.0f / l0, inv1 = 1.0f / l1;
    size_t ob0 = (((size_t)b * S + s0 + r0) * NH + h) * HD;
    size_t ob1 = (((size_t)b * S + s0 + r1) * NH + h) * HD;
#pragma unroll
    for (int j = 0; j < 16; j++) {
        int d = j * 8 + (lane & 3) * 2;
        float o0 = acc[j][0] * inv0, o1 = acc[j][1] * inv0;
        float o2 = acc[j][2] * inv1, o3 = acc[j][3] * inv1;
        __nv_bfloat16 h0, h1, h2, h3, q0b, q1b, q2b, q3b;
        split1(o0, h0, q0b);
        split1(o1, h1, q1b);
        split1(o2, h2, q2b);
        split1(o3, h3, q3b);
        *(uint32_t*)(g_oh + ob0 + d) = packbf(h0, h1);
        *(uint32_t*)(g_ol + ob0 + d) = packbf(q0b, q1b);
        *(uint32_t*)(g_oh + ob1 + d) = packbf(h2, h3);
        *(uint32_t*)(g_ol + ob1 + d) = packbf(q2b, q3b);
    }
}

// ---------------------------------------------------------------------------
extern "C" void kernel_launch(void* const* d_in, const int* in_sizes, int n_in,
                              void* d_out, int out_size) {
    const float* x  = (const float*)d_in[0];
    const float* wq = (const float*)d_in[1];
    const float* wk = (const float*)d_in[2];
    const float* wv = (const float*)d_in[3];
    const float* wo = (const float*)d_in[4];
    float* out = (float*)d_out;

    float *Q, *K, *V;
    cudaGetSymbolAddress((void**)&Q, g_Q);
    cudaGetSymbolAddress((void**)&K, g_K);
    cudaGetSymbolAddress((void**)&V, g_V);

    __nv_bfloat16 *xh, *xl, *wqh, *wql, *wkh, *wkl, *wvh, *wvl, *woh, *wol;
    __nv_bfloat16 *Qh, *Ql, *Kh, *Kl, *Vh, *Vl;
    cudaGetSymbolAddress((void**)&xh, g_xh);
    cudaGetSymbolAddress((void**)&xl, g_xl);
    cudaGetSymbolAddress((void**)&wqh, g_wqh);
    cudaGetSymbolAddress((void**)&wql, g_wql);
    cudaGetSymbolAddress((void**)&wkh, g_wkh);
    cudaGetSymbolAddress((void**)&wkl, g_wkl);
    cudaGetSymbolAddress((void**)&wvh, g_wvh);
    cudaGetSymbolAddress((void**)&wvl, g_wvl);
    cudaGetSymbolAddress((void**)&woh, g_woh);
    cudaGetSymbolAddress((void**)&wol, g_wol);
    cudaGetSymbolAddress((void**)&Qh, g_Qh);
    cudaGetSymbolAddress((void**)&Ql, g_Ql);
    cudaGetSymbolAddress((void**)&Kh, g_Kh);
    cudaGetSymbolAddress((void**)&Kl, g_Kl);
    cudaGetSymbolAddress((void**)&Vh, g_Vh);
    cudaGetSymbolAddress((void**)&Vl, g_Vl);

    const int M = B * S;  // 4096
    cudaFuncSetAttribute(attn_mma_kernel,
                         cudaFuncAttributeMaxDynamicSharedMemorySize, AT_SMEM_BYTES);
    cudaFuncSetAttribute(gemm_qkv_kernel,
                         cudaFuncAttributeMaxDynamicSharedMemorySize, GEMM_SMEM);
    cudaFuncSetAttribute(gemm_out_kernel,
                         cudaFuncAttributeMaxDynamicSharedMemorySize, GEMM_SMEM);

    rope_table_kernel<<<(S * 64 + 255) / 256, 256>>>();

    // pre-split inputs/weights
    {
        int n4;
        n4 = (M * HID) / 4;
        split_kernel<<<(n4 + 255) / 256, 256>>>(x, xh, xl, n4);
        n4 = (HID * NH * HD) / 4;
        split_kernel<<<(n4 + 255) / 256, 256>>>(wq, wqh, wql, n4);
        n4 = (HID * NKV * HD) / 4;
        split_kernel<<<(n4 + 255) / 256, 256>>>(wk, wkh, wkl, n4);
        split_kernel<<<(n4 + 255) / 256, 256>>>(wv, wvh, wvl, n4);
        n4 = (NH * HD * HID) / 4;
        split_kernel<<<(n4 + 255) / 256, 256>>>(wo, woh, wol, n4);
    }

    // fused Q/K/V projections (pipelined)
    gemm_qkv_kernel<<<dim3(24, 32), 256, GEMM_SMEM>>>();

    // RoPE
    {
        int totq = B * S * NH * 64;
        rope_apply_kernel<<<(totq + 255) / 256, 256>>>(Q, NH, totq);
        int totk = B * S * NKV * 64;
        rope_apply_kernel<<<(totk + 255) / 256, 256>>>(K, NKV, totk);
    }

    // split post-RoPE Q/K and V
    {
        int n4 = (B * S * NH * HD) / 4;
        split_kernel<<<(n4 + 255) / 256, 256>>>(Q, Qh, Ql, n4);
        n4 = (B * S * NKV * HD) / 4;
        split_kernel<<<(n4 + 255) / 256, 256>>>(K, Kh, Kl, n4);
        split_kernel<<<(n4 + 255) / 256, 256>>>(V, Vh, Vl, n4);
    }

    // chunk means + selection
    kmean_kernel<<<B * NCH * NKV, 128>>>();
    select_kernel<<<(B * NH * S) / 8, 256>>>();

    // tensor-core sparse attention
    attn_mma_kernel<<<dim3(S / AQ, NH, B), 256, AT_SMEM_BYTES>>>();

    // output projection (pipelined)
    gemm_out_kernel<<<dim3(16, 32), 256, GEMM_SMEM>>>(out);
}

// round 10
// speedup vs baseline: 5.1341x; 1.0473x over previous
#include <cuda_runtime.h>
#include <cuda_bf16.h>
#include <math.h>
#include <stdint.h>

// Problem constants
#define B 2
#define S 2048
#define HID 2048
#define NH 16
#define NKV 4
#define HD 128
#define CHUNK 256
#define NCH 8

// Scratch (static device allocations; no cudaMalloc allowed)
__device__ float g_Q[(size_t)B * S * NH * HD];
__device__ float g_K[(size_t)B * S * NKV * HD];
__device__ float g_V[(size_t)B * S * NKV * HD];
__device__ float g_kmean[(size_t)B * NCH * NKV * HD];
__device__ unsigned g_sel[(size_t)B * NH * S];
__device__ float g_rc[(size_t)S * 64];
__device__ float g_rs[(size_t)S * 64];

// bf16 hi/lo split copies
__device__ __nv_bfloat16 g_xh[(size_t)B * S * HID];
__device__ __nv_bfloat16 g_xl[(size_t)B * S * HID];
__device__ __nv_bfloat16 g_wqh[(size_t)HID * NH * HD];
__device__ __nv_bfloat16 g_wql[(size_t)HID * NH * HD];
__device__ __nv_bfloat16 g_wkh[(size_t)HID * NKV * HD];
__device__ __nv_bfloat16 g_wkl[(size_t)HID * NKV * HD];
__device__ __nv_bfloat16 g_wvh[(size_t)HID * NKV * HD];
__device__ __nv_bfloat16 g_wvl[(size_t)HID * NKV * HD];
__device__ __nv_bfloat16 g_woh[(size_t)NH * HD * HID];
__device__ __nv_bfloat16 g_wol[(size_t)NH * HD * HID];
__device__ __nv_bfloat16 g_oh[(size_t)B * S * NH * HD];
__device__ __nv_bfloat16 g_ol[(size_t)B * S * NH * HD];
// post-RoPE bf16 splits for attention
__device__ __nv_bfloat16 g_Qh[(size_t)B * S * NH * HD];
__device__ __nv_bfloat16 g_Ql[(size_t)B * S * NH * HD];
__device__ __nv_bfloat16 g_Kh[(size_t)B * S * NKV * HD];
__device__ __nv_bfloat16 g_Kl[(size_t)B * S * NKV * HD];
__device__ __nv_bfloat16 g_Vh[(size_t)B * S * NKV * HD];
__device__ __nv_bfloat16 g_Vl[(size_t)B * S * NKV * HD];

// ===========================================================================
// helpers
// ===========================================================================
__device__ __forceinline__ uint32_t smem_u32(const void* p) {
    uint32_t a;
    asm("{ .reg .u64 t; cvta.to.shared.u64 t, %1; cvt.u32.u64 %0, t; }"
        : "=r"(a) : "l"(p));
    return a;
}

__device__ __forceinline__ void ldsm4(uint32_t* r, uint32_t addr) {
    asm volatile("ldmatrix.sync.aligned.m8n8.x4.shared.b16 {%0,%1,%2,%3}, [%4];"
                 : "=r"(r[0]), "=r"(r[1]), "=r"(r[2]), "=r"(r[3]) : "r"(addr));
}
__device__ __forceinline__ void ldsm4t(uint32_t* r, uint32_t addr) {
    asm volatile("ldmatrix.sync.aligned.m8n8.x4.trans.shared.b16 {%0,%1,%2,%3}, [%4];"
                 : "=r"(r[0]), "=r"(r[1]), "=r"(r[2]), "=r"(r[3]) : "r"(addr));
}
__device__ __forceinline__ void mma16816(float* c, const uint32_t* a,
                                         uint32_t b0, uint32_t b1) {
    asm volatile(
        "mma.sync.aligned.m16n8k16.row.col.f32.bf16.bf16.f32 "
        "{%0,%1,%2,%3}, {%4,%5,%6,%7}, {%8,%9}, {%0,%1,%2,%3};"
        : "+f"(c[0]), "+f"(c[1]), "+f"(c[2]), "+f"(c[3])
        : "r"(a[0]), "r"(a[1]), "r"(a[2]), "r"(a[3]), "r"(b0), "r"(b1));
}
__device__ __forceinline__ void cpa16(uint32_t s, const void* g) {
    asm volatile("cp.async.cg.shared.global [%0], [%1], 16;" :: "r"(s), "l"(g));
}

__device__ __forceinline__ void split1(float a, __nv_bfloat16& h, __nv_bfloat16& l) {
    h = __float2bfloat16_rn(a);
    l = __float2bfloat16_rn(a - __bfloat162float(h));
}
__device__ __forceinline__ uint32_t packbf(__nv_bfloat16 lo, __nv_bfloat16 hi) {
    return ((uint32_t)__bfloat16_as_ushort(hi) << 16) | __bfloat16_as_ushort(lo);
}

// ---------------------------------------------------------------------------
// split kernel: fp32 -> bf16 hi + lo
// ---------------------------------------------------------------------------
__global__ void split_kernel(const float* __restrict__ in,
                             __nv_bfloat16* __restrict__ hi,
                             __nv_bfloat16* __restrict__ lo, int n4) {
    int i = blockIdx.x * blockDim.x + threadIdx.x;
    if (i >= n4) return;
    float4 v = ((const float4*)in)[i];
    __nv_bfloat16 h0, h1, h2, h3, l0, l1, l2, l3;
    split1(v.x, h0, l0);
    split1(v.y, h1, l1);
    split1(v.z, h2, l2);
    split1(v.w, h3, l3);
    ((uint2*)hi)[i] = make_uint2(packbf(h0, h1), packbf(h2, h3));
    ((uint2*)lo)[i] = make_uint2(packbf(l0, l1), packbf(l2, l3));
}

// ===========================================================================
// bf16x3 GEMM, cp.async 3-stage pipeline, single barrier per iteration.
// ===========================================================================
#define GBK 32
#define PAH 0
#define PAL 10240
#define PBH 20480
#define PBL 29184
#define PSTAGE 37888
#define GEMM_SMEM (3 * PSTAGE)

__device__ __forceinline__ void gemm_issue(
    uint32_t st, const __nv_bfloat16* Ah, const __nv_bfloat16* Al,
    const __nv_bfloat16* Bh, const __nv_bfloat16* Bl,
    int bm, int bn, int k0, int N, int K, int tid) {
#pragma unroll
    for (int i = 0; i < 2; i++) {
        int c = tid + i * 256;
        int row = c >> 2, q = c & 3;
        size_t g = (size_t)(bm + row) * K + k0 + q * 8;
        cpa16(st + PAH + row * 80 + q * 16, Ah + g);
        cpa16(st + PAL + row * 80 + q * 16, Al + g);
    }
#pragma unroll
    for (int i = 0; i < 2; i++) {
        int c = tid + i * 256;
        int row = c >> 4, q = c & 15;
        size_t g = (size_t)(k0 + row) * N + bn + q * 8;
        cpa16(st + PBH + row * 272 + q * 16, Bh + g);
        cpa16(st + PBL + row * 272 + q * 16, Bl + g);
    }
    asm volatile("cp.async.commit_group;");
}

__device__ __forceinline__ void gemm_body(
    const __nv_bfloat16* __restrict__ Ah, const __nv_bfloat16* __restrict__ Al,
    const __nv_bfloat16* __restrict__ Bh, const __nv_bfloat16* __restrict__ Bl,
    float* __restrict__ C, int N, int K, int bm, int bn, char* smem) {
    int tid = threadIdx.x;
    int lane = tid & 31, wid = tid >> 5;
    int wm = wid & 3, wn = wid >> 2;

    float acc[2][8][4];
#pragma unroll
    for (int i = 0; i < 2; i++)
#pragma unroll
        for (int j = 0; j < 8; j++)
#pragma unroll
            for (int k = 0; k < 4; k++) acc[i][j][k] = 0.f;

    uint32_t sb = smem_u32(smem);
    int l15 = lane & 15, l16 = lane >> 4;
    uint32_t a_off = (uint32_t)(wm * 32 + l15) * 80 + l16 * 16;
    uint32_t b_off = (uint32_t)(((lane >> 3) & 1) * 8 + (lane & 7)) * 272
                   + wn * 128 + l16 * 16;

    int niter = K / GBK;
    gemm_issue(sb, Ah, Al, Bh, Bl, bm, bn, 0, N, K, tid);
    gemm_issue(sb + PSTAGE, Ah, Al, Bh, Bl, bm, bn, GBK, N, K, tid);

    int stg = 0;   // it % 3
    for (int it = 0; it < niter; it++) {
        if (it + 1 < niter)
            asm volatile("cp.async.wait_group 1;");
        else
            asm volatile("cp.async.wait_group 0;");
        __syncthreads();
        if (it + 2 < niter) {
            int pst = stg + 2;
            if (pst >= 3) pst -= 3;
            gemm_issue(sb + pst * PSTAGE, Ah, Al, Bh, Bl,
                       bm, bn, (it + 2) * GBK, N, K, tid);
        }

        uint32_t st = sb + stg * PSTAGE;
        uint32_t ash = st + PAH, asl = st + PAL;
        uint32_t bsh = st + PBH, bsl = st + PBL;
#pragma unroll
        for (int ka = 0; ka < 2; ka++) {
            uint32_t ahf[2][4], alf[2][4];
            ldsm4(ahf[0], ash + a_off + ka * 32);
            ldsm4(ahf[1], ash + a_off + ka * 32 + 16 * 80);
            ldsm4(alf[0], asl + a_off + ka * 32);
            ldsm4(alf[1], asl + a_off + ka * 32 + 16 * 80);
#pragma unroll
            for (int nh2 = 0; nh2 < 2; nh2++) {
                uint32_t bhf[2][4], blf[2][4];
                uint32_t bo = b_off + ka * 16 * 272 + nh2 * 64;
                ldsm4t(bhf[0], bsh + bo);
                ldsm4t(bhf[1], bsh + bo + 32);
                ldsm4t(blf[0], bsl + bo);
                ldsm4t(blf[1], bsl + bo + 32);
#pragma unroll
                for (int j = 0; j < 2; j++)
#pragma unroll
                    for (int ma = 0; ma < 2; ma++)
#pragma unroll
                        for (int sub = 0; sub < 2; sub++)
                            mma16816(acc[ma][(nh2 * 2 + j) * 2 + sub], ahf[ma],
                                     bhf[j][sub * 2], bhf[j][sub * 2 + 1]);
#pragma unroll
                for (int j = 0; j < 2; j++)
#pragma unroll
                    for (int ma = 0; ma < 2; ma++)
#pragma unroll
                        for (int sub = 0; sub < 2; sub++)
                            mma16816(acc[ma][(nh2 * 2 + j) * 2 + sub], ahf[ma],
                                     blf[j][sub * 2], blf[j][sub * 2 + 1]);
#pragma unroll
                for (int j = 0; j < 2; j++)
#pragma unroll
                    for (int ma = 0; ma < 2; ma++)
#pragma unroll
                        for (int sub = 0; sub < 2; sub++)
                            mma16816(acc[ma][(nh2 * 2 + j) * 2 + sub], alf[ma],
                                     bhf[j][sub * 2], bhf[j][sub * 2 + 1]);
            }
        }
        if (++stg == 3) stg = 0;
    }

#pragma unroll
    for (int ma = 0; ma < 2; ma++) {
        int row = bm + wm * 32 + ma * 16 + (lane >> 2);
#pragma unroll
        for (int na = 0; na < 8; na++) {
            int col = bn + wn * 64 + na * 8 + (lane & 3) * 2;
            *(float2*)(C + (size_t)row * N + col) =
                make_float2(acc[ma][na][0], acc[ma][na][1]);
            *(float2*)(C + (size_t)(row + 8) * N + col) =
                make_float2(acc[ma][na][2], acc[ma][na][3]);
        }
    }
}

__global__ __launch_bounds__(256, 2)
void gemm_qkv_kernel() {
    extern __shared__ char smem[];
    int bx = blockIdx.x;
    const __nv_bfloat16 *Bh, *Bl;
    float* C;
    int N, bn;
    if (bx < 16) {
        Bh = g_wqh; Bl = g_wql; C = g_Q; N = NH * HD; bn = bx * 128;
    } else if (bx < 20) {
        Bh = g_wkh; Bl = g_wkl; C = g_K; N = NKV * HD; bn = (bx - 16) * 128;
    } else {
        Bh = g_wvh; Bl = g_wvl; C = g_V; N = NKV * HD; bn = (bx - 20) * 128;
    }
    gemm_body(g_xh, g_xl, Bh, Bl, C, N, HID, blockIdx.y * 128, bn, smem);
}

__global__ __launch_bounds__(256, 2)
void gemm_out_kernel(float* __restrict__ C) {
    extern __shared__ char smem[];
    gemm_body(g_oh, g_ol, g_woh, g_wol, C, HID, NH * HD,
              blockIdx.y * 128, blockIdx.x * 128, smem);
}

// ---------------------------------------------------------------------------
// RoPE table + apply (apply also emits bf16 hi/lo splits)
// ---------------------------------------------------------------------------
__global__ void rope_table_kernel() {
    int i = blockIdx.x * blockDim.x + threadIdx.x;
    if (i >= S * 64) return;
    int j = i & 63;
    int s = i >> 6;
    double ifd = exp(-((double)(2 * j) / 128.0) * log(10000.0));
    float invf = (float)ifd;
    float ang = (float)s * invf;
    double cd, sd;
    sincos((double)ang, &sd, &cd);
    g_rc[i] = (float)cd;
    g_rs[i] = (float)sd;
}

__global__ void rope_apply_split_kernel(float* __restrict__ x,
                                        __nv_bfloat16* __restrict__ hi,
                                        __nv_bfloat16* __restrict__ lo,
                                        int heads, int total) {
    int i = blockIdx.x * blockDim.x + threadIdx.x;
    if (i >= total) return;
    int j = i & 63;
    int rest = i >> 6;
    int h = rest % heads;
    int bs = rest / heads;
    int s = bs & (S - 1);
    float c = g_rc[s * 64 + j];
    float sn = g_rs[s * 64 + j];
    size_t base = ((size_t)bs * heads + h) * HD;
    float x1 = x[base + j], x2 = x[base + j + 64];
    float y1 = x1 * c - x2 * sn;
    float y2 = x2 * c + x1 * sn;
    x[base + j] = y1;
    x[base + j + 64] = y2;
    __nv_bfloat16 h1, l1, h2, l2;
    split1(y1, h1, l1);
    split1(y2, h2, l2);
    hi[base + j] = h1;
    lo[base + j] = l1;
    hi[base + j + 64] = h2;
    lo[base + j + 64] = l2;
}

// ---------------------------------------------------------------------------
// Per-chunk K mean + selection
// ---------------------------------------------------------------------------
__global__ void kmean_kernel() {
    int id = blockIdx.x;
    int kvh = id & 3;
    int n = (id >> 2) & 7;
    int b = id >> 5;
    int d = threadIdx.x;
    const float* base = g_K + (((size_t)b * S + n * CHUNK) * NKV + kvh) * HD + d;
    float s = 0.f;
#pragma unroll 8
    for (int i = 0; i < CHUNK; i++) s += base[(size_t)i * NKV * HD];
    g_kmean[((b * NCH + n) * NKV + kvh) * HD + d] = s * (1.0f / CHUNK);
}

__global__ void select_kernel() {
    int w = blockIdx.x * (blockDim.x >> 5) + (threadIdx.x >> 5);
    int lane = threadIdx.x & 31;
    int s = w & (S - 1);
    int h = (w >> 11) & (NH - 1);
    int b = w >> 15;
    int kvh = h >> 2;
    int qc = s >> 8;

    const float* q = g_Q + (((size_t)b * S + s) * NH + h) * HD;
    float4 qv = *(const float4*)(q + lane * 4);
    float g[8];
    for (int n = 0; n < qc; n++) {
        const float* km = g_kmean + ((b * NCH + n) * NKV + kvh) * HD;
        float4 kv = *(const float4*)(km + lane * 4);
        float p = qv.x * kv.x + qv.y * kv.y + qv.z * kv.z + qv.w * kv.w;
#pragma unroll
        for (int o = 16; o; o >>= 1) p += __shfl_xor_sync(0xffffffffu, p, o);
        g[n] = p;
    }
    if (lane == 0) {
        unsigned sel = 1u << qc;
        for (int it = 0; it < 3; it++) {
            float best = 0.f;
            int bi = -1;
            for (int n = 0; n < qc; n++)
                if (!((sel >> n) & 1) && (bi < 0 || g[n] > best)) { best = g[n]; bi = n; }
            if (bi >= 0) sel |= 1u << bi;
        }
        g_sel[w] = sel;
    }
}

// ===========================================================================
// Tensor-core sparse flash attention, 3-stage cp.async K/V pipeline +
// per-warp chunk skip.
// ===========================================================================
#define AQ 128
#define AK 32
#define ASTR 136

#define KVSTAGE_B (4 * AK * ASTR * 2)       // bytes per KV stage (34816)
#define OFF_KH 0
#define OFF_KL (AK * ASTR * 2)
#define OFF_VH (2 * AK * ASTR * 2)
#define OFF_VL (3 * AK * ASTR * 2)
#define AT_Q_ELEMS (2 * AQ * ASTR)
#define AT_KV0_B (AT_Q_ELEMS * 2)
#define AT_BF16_B (AT_KV0_B + 3 * KVSTAGE_B)
#define AT_SMEM_BYTES (AT_BF16_B + AQ * 4 + 16 + 160)

__device__ __forceinline__ void attn_issue_kv(uint32_t st, int b, int kvh,
                                              int kt, int tid) {
    int row = tid >> 3;
    size_t gk = (((size_t)b * S + kt * AK + row) * NKV + kvh) * HD;
#pragma unroll
    for (int i = 0; i < 2; i++) {
        int g = (tid & 7) * 2 + i;
        uint32_t off = row * 272 + g * 16;
        cpa16(st + OFF_KH + off, g_Kh + gk + g * 8);
        cpa16(st + OFF_KL + off, g_Kl + gk + g * 8);
        cpa16(st + OFF_VH + off, g_Vh + gk + g * 8);
        cpa16(st + OFF_VL + off, g_Vl + gk + g * 8);
    }
    asm volatile("cp.async.commit_group;");
}

__global__ __launch_bounds__(256)
void attn_mma_kernel() {
    extern __shared__ __align__(16) char smc[];
    __nv_bfloat16* sQh = (__nv_bfloat16*)smc;
    __nv_bfloat16* sQl = sQh + AQ * ASTR;
    unsigned* selq = (unsigned*)(smc + AT_BF16_B);
    unsigned* selu_p = selq + AQ;
    int* cnt_p = (int*)(selu_p + 1);
    short* list = (short*)(cnt_p + 1);

    int qt = gridDim.x - 1 - blockIdx.x;
    int h = blockIdx.y, b = blockIdx.z;
    int kvh = h >> 2;
    int tid = threadIdx.x, lane = tid & 31, w = tid >> 5;
    int s0 = qt * AQ;
    int qc = s0 >> 8;

    // ---- stage Q ----
    {
        int r = tid >> 1, half = tid & 1;
        size_t gq = (((size_t)b * S + s0 + r) * NH + h) * HD + half * 64;
#pragma unroll
        for (int i = 0; i < 8; i++) {
            *(uint4*)&sQh[r * ASTR + half * 64 + i * 8] = *(const uint4*)(g_Qh + gq + i * 8);
            *(uint4*)&sQl[r * ASTR + half * 64 + i * 8] = *(const uint4*)(g_Ql + gq + i * 8);
        }
    }
    if (tid == 0) *selu_p = 0;
    __syncthreads();
    if (tid < AQ) {
        unsigned sv = g_sel[((size_t)(b * NH + h) << 11) + s0 + tid];
        selq[tid] = sv;
        atomicOr(selu_p, sv);
    }
    __syncthreads();
    // build active tile list
    if (tid == 0) {
        unsigned selu = *selu_p;
        int nkt = (s0 >> 5) + 4;
        int c = 0;
        for (int kt = 0; kt < nkt; kt++) {
            int n = kt >> 3;
            if (n < qc && !((selu >> n) & 1)) continue;
            list[c++] = (short)kt;
        }
        *cnt_p = c;
    }
    __syncthreads();
    int cnt = *cnt_p;

    // per-warp chunk union
    unsigned selw = 0;
#pragma unroll
    for (int i = 0; i < 16; i++) selw |= selq[w * 16 + i];

    uint32_t kv0 = smem_u32(smc + AT_KV0_B);
    attn_issue_kv(kv0, b, kvh, list[0], tid);
    if (cnt > 1) attn_issue_kv(kv0 + KVSTAGE_B, b, kvh, list[1], tid);

    float acc[16][4];
#pragma unroll
    for (int j = 0; j < 16; j++)
#pragma unroll
        for (int k = 0; k < 4; k++) acc[j][k] = 0.f;
    float m0 = -1e30f, m1 = -1e30f, l0 = 0.f, l1 = 0.f;

    const float scale = 0.08838834764831845f;

    uint32_t qh_b = smem_u32(sQh), ql_b = smem_u32(sQl);
    uint32_t a_off = (uint32_t)(w * 16 + (lane & 15)) * 272 + (lane >> 4) * 16;
    uint32_t k_off = (uint32_t)((lane & 7) + (lane >> 4) * 8) * 272 + ((lane >> 3) & 1) * 16;
    uint32_t v_off = (uint32_t)(((lane >> 3) & 1) * 8 + (lane & 7)) * 272 + (lane >> 4) * 16;

    int r0 = w * 16 + (lane >> 2);
    int r1 = r0 + 8;

    int stg = 0;
    for (int i = 0; i < cnt; i++) {
        if (i + 1 < cnt)
            asm volatile("cp.async.wait_group 1;");
        else
            asm volatile("cp.async.wait_group 0;");
        __syncthreads();
        if (i + 2 < cnt) {
            int pst = stg + 2;
            if (pst >= 3) pst -= 3;
            attn_issue_kv(kv0 + pst * KVSTAGE_B, b, kvh, list[i + 2], tid);
        }

        int kt = list[i];
        int n = kt >> 3;
        bool past = (n < qc);
        uint32_t st = kv0 + stg * KVSTAGE_B;
        if (++stg == 3) stg = 0;

        if (past && !((selw >> n) & 1)) continue;  // warp-level skip

        uint32_t kh_b = st + OFF_KH, kl_b = st + OFF_KL;
        uint32_t vh_b = st + OFF_VH, vl_b = st + OFF_VL;

        float s[4][4];
#pragma unroll
        for (int nt = 0; nt < 4; nt++)
#pragma unroll
            for (int k = 0; k < 4; k++) s[nt][k] = 0.f;
#pragma unroll
        for (int ka = 0; ka < 8; ka++) {
            uint32_t aqh[4], aql[4], bh0[4], bh1[4], bl0[4], bl1[4];
            ldsm4(aqh, qh_b + a_off + ka * 32);
            ldsm4(aql, ql_b + a_off + ka * 32);
            ldsm4(bh0, kh_b + k_off + ka * 32);
            ldsm4(bh1, kh_b + k_off + 16 * 272 + ka * 32);
            ldsm4(bl0, kl_b + k_off + ka * 32);
            ldsm4(bl1, kl_b + k_off + 16 * 272 + ka * 32);
            mma16816(s[0], aqh, bh0[0], bh0[1]);
            mma16816(s[1], aqh, bh0[2], bh0[3]);
            mma16816(s[2], aqh, bh1[0], bh1[1]);
            mma16816(s[3], aqh, bh1[2], bh1[3]);
            mma16816(s[0], aqh, bl0[0], bl0[1]);
            mma16816(s[1], aqh, bl0[2], bl0[3]);
            mma16816(s[2], aqh, bl1[0], bl1[1]);
            mma16816(s[3], aqh, bl1[2], bl1[3]);
            mma16816(s[0], aql, bh0[0], bh0[1]);
            mma16816(s[1], aql, bh0[2], bh0[3]);
            mma16816(s[2], aql, bh1[0], bh1[1]);
            mma16816(s[3], aql, bh1[2], bh1[3]);
        }

        if (past) {
            bool ok0 = (selq[r0] >> n) & 1, ok1 = (selq[r1] >> n) & 1;
#pragma unroll
            for (int nt = 0; nt < 4; nt++) {
                s[nt][0] = ok0 ? s[nt][0] * scale : -3.0e38f;
                s[nt][1] = ok0 ? s[nt][1] * scale : -3.0e38f;
                s[nt][2] = ok1 ? s[nt][2] * scale : -3.0e38f;
                s[nt][3] = ok1 ? s[nt][3] * scale : -3.0e38f;
            }
        } else {
            int q0 = s0 + r0, q1 = s0 + r1;
#pragma unroll
            for (int nt = 0; nt < 4; nt++) {
                int t = kt * 32 + nt * 8 + (lane & 3) * 2;
                s[nt][0] = (t     <= q0) ? s[nt][0] * scale : -3.0e38f;
                s[nt][1] = (t + 1 <= q0) ? s[nt][1] * scale : -3.0e38f;
                s[nt][2] = (t     <= q1) ? s[nt][2] * scale : -3.0e38f;
                s[nt][3] = (t + 1 <= q1) ? s[nt][3] * scale : -3.0e38f;
            }
        }

        float mx0 = -3.0e38f, mx1 = -3.0e38f;
#pragma unroll
        for (int nt = 0; nt < 4; nt++) {
            mx0 = fmaxf(mx0, fmaxf(s[nt][0], s[nt][1]));
            mx1 = fmaxf(mx1, fmaxf(s[nt][2], s[nt][3]));
        }
        mx0 = fmaxf(mx0, __shfl_xor_sync(0xffffffffu, mx0, 1));
        mx0 = fmaxf(mx0, __shfl_xor_sync(0xffffffffu, mx0, 2));
        mx1 = fmaxf(mx1, __shfl_xor_sync(0xffffffffu, mx1, 1));
        mx1 = fmaxf(mx1, __shfl_xor_sync(0xffffffffu, mx1, 2));
        float mn0 = fmaxf(m0, mx0), mn1 = fmaxf(m1, mx1);
        float f0 = __expf(m0 - mn0), f1 = __expf(m1 - mn1);

        float sum0 = 0.f, sum1 = 0.f;
        uint32_t ph[4][2], pl[4][2];
#pragma unroll
        for (int nt = 0; nt < 4; nt++) {
            float p0 = __expf(s[nt][0] - mn0);
            float p1 = __expf(s[nt][1] - mn0);
            float p2 = __expf(s[nt][2] - mn1);
            float p3 = __expf(s[nt][3] - mn1);
            sum0 += p0 + p1;
            sum1 += p2 + p3;
            __nv_bfloat16 h0, h1, h2, h3, q0b, q1b, q2b, q3b;
            split1(p0, h0, q0b);
            split1(p1, h1, q1b);
            split1(p2, h2, q2b);
            split1(p3, h3, q3b);
            ph[nt][0] = packbf(h0, h1);
            ph[nt][1] = packbf(h2, h3);
            pl[nt][0] = packbf(q0b, q1b);
            pl[nt][1] = packbf(q2b, q3b);
        }
        sum0 += __shfl_xor_sync(0xffffffffu, sum0, 1);
        sum0 += __shfl_xor_sync(0xffffffffu, sum0, 2);
        sum1 += __shfl_xor_sync(0xffffffffu, sum1, 1);
        sum1 += __shfl_xor_sync(0xffffffffu, sum1, 2);
        l0 = l0 * f0 + sum0;
        l1 = l1 * f1 + sum1;
        m0 = mn0;
        m1 = mn1;
#pragma unroll
        for (int j = 0; j < 16; j++) {
            acc[j][0] *= f0;
            acc[j][1] *= f0;
            acc[j][2] *= f1;
            acc[j][3] *= f1;
        }

#pragma unroll
        for (int kg = 0; kg < 2; kg++) {
            uint32_t aPh[4] = {ph[kg * 2][0], ph[kg * 2][1], ph[kg * 2 + 1][0], ph[kg * 2 + 1][1]};
            uint32_t aPl[4] = {pl[kg * 2][0], pl[kg * 2][1], pl[kg * 2 + 1][0], pl[kg * 2 + 1][1]};
#pragma unroll
            for (int dn = 0; dn < 8; dn++) {
                uint32_t bvh[4], bvl[4];
                ldsm4t(bvh, vh_b + v_off + kg * 16 * 272 + dn * 32);
                ldsm4t(bvl, vl_b + v_off + kg * 16 * 272 + dn * 32);
                mma16816(acc[dn * 2],     aPh, bvh[0], bvh[1]);
                mma16816(acc[dn * 2 + 1], aPh, bvh[2], bvh[3]);
                mma16816(acc[dn * 2],     aPh, bvl[0], bvl[1]);
                mma16816(acc[dn * 2 + 1], aPh, bvl[2], bvl[3]);
                mma16816(acc[dn * 2],     aPl, bvh[0], bvh[1]);
                mma16816(acc[dn * 2 + 1], aPl, bvh[2], bvh[3]);
            }
        }
    }

    float inv0 = 1.0f / l0, inv1 = 1.0f / l1;
    size_t ob0 = (((size_t)b * S + s0 + r0) * NH + h) * HD;
    size_t ob1 = (((size_t)b * S + s0 + r1) * NH + h) * HD;
#pragma unroll
    for (int j = 0; j < 16; j++) {
        int d = j * 8 + (lane & 3) * 2;
        float o0 = acc[j][0] * inv0, o1 = acc[j][1] * inv0;
        float o2 = acc[j][2] * inv1, o3 = acc[j][3] * inv1;
        __nv_bfloat16 h0, h1, h2, h3, q0b, q1b, q2b, q3b;
        split1(o0, h0, q0b);
        split1(o1, h1, q1b);
        split1(o2, h2, q2b);
        split1(o3, h3, q3b);
        *(uint32_t*)(g_oh + ob0 + d) = packbf(h0, h1);
        *(uint32_t*)(g_ol + ob0 + d) = packbf(q0b, q1b);
        *(uint32_t*)(g_oh + ob1 + d) = packbf(h2, h3);
        *(uint32_t*)(g_ol + ob1 + d) = packbf(q2b, q3b);
    }
}

// ---------------------------------------------------------------------------
extern "C" void kernel_launch(void* const* d_in, const int* in_sizes, int n_in,
                              void* d_out, int out_size) {
    const float* x  = (const float*)d_in[0];
    const float* wq = (const float*)d_in[1];
    const float* wk = (const float*)d_in[2];
    const float* wv = (const float*)d_in[3];
    const float* wo = (const float*)d_in[4];
    float* out = (float*)d_out;

    float *Q, *K, *V;
    cudaGetSymbolAddress((void**)&Q, g_Q);
    cudaGetSymbolAddress((void**)&K, g_K);
    cudaGetSymbolAddress((void**)&V, g_V);

    __nv_bfloat16 *xh, *xl, *wqh, *wql, *wkh, *wkl, *wvh, *wvl, *woh, *wol;
    __nv_bfloat16 *Qh, *Ql, *Kh, *Kl, *Vh, *Vl;
    cudaGetSymbolAddress((void**)&xh, g_xh);
    cudaGetSymbolAddress((void**)&xl, g_xl);
    cudaGetSymbolAddress((void**)&wqh, g_wqh);
    cudaGetSymbolAddress((void**)&wql, g_wql);
    cudaGetSymbolAddress((void**)&wkh, g_wkh);
    cudaGetSymbolAddress((void**)&wkl, g_wkl);
    cudaGetSymbolAddress((void**)&wvh, g_wvh);
    cudaGetSymbolAddress((void**)&wvl, g_wvl);
    cudaGetSymbolAddress((void**)&woh, g_woh);
    cudaGetSymbolAddress((void**)&wol, g_wol);
    cudaGetSymbolAddress((void**)&Qh, g_Qh);
    cudaGetSymbolAddress((void**)&Ql, g_Ql);
    cudaGetSymbolAddress((void**)&Kh, g_Kh);
    cudaGetSymbolAddress((void**)&Kl, g_Kl);
    cudaGetSymbolAddress((void**)&Vh, g_Vh);
    cudaGetSymbolAddress((void**)&Vl, g_Vl);

    const int M = B * S;  // 4096
    cudaFuncSetAttribute(attn_mma_kernel,
                         cudaFuncAttributeMaxDynamicSharedMemorySize, AT_SMEM_BYTES);
    cudaFuncSetAttribute(gemm_qkv_kernel,
                         cudaFuncAttributeMaxDynamicSharedMemorySize, GEMM_SMEM);
    cudaFuncSetAttribute(gemm_out_kernel,
                         cudaFuncAttributeMaxDynamicSharedMemorySize, GEMM_SMEM);

    rope_table_kernel<<<(S * 64 + 255) / 256, 256>>>();

    // pre-split inputs/weights
    {
        int n4;
        n4 = (M * HID) / 4;
        split_kernel<<<(n4 + 255) / 256, 256>>>(x, xh, xl, n4);
        n4 = (HID * NH * HD) / 4;
        split_kernel<<<(n4 + 255) / 256, 256>>>(wq, wqh, wql, n4);
        n4 = (HID * NKV * HD) / 4;
        split_kernel<<<(n4 + 255) / 256, 256>>>(wk, wkh, wkl, n4);
        split_kernel<<<(n4 + 255) / 256, 256>>>(wv, wvh, wvl, n4);
        n4 = (NH * HD * HID) / 4;
        split_kernel<<<(n4 + 255) / 256, 256>>>(wo, woh, wol, n4);
    }

    // fused Q/K/V projections (3-stage pipelined)
    gemm_qkv_kernel<<<dim3(24, 32), 256, GEMM_SMEM>>>();

    // RoPE + direct bf16 hi/lo emission
    {
        int totq = B * S * NH * 64;
        rope_apply_split_kernel<<<(totq + 255) / 256, 256>>>(Q, Qh, Ql, NH, totq);
        int totk = B * S * NKV * 64;
        rope_apply_split_kernel<<<(totk + 255) / 256, 256>>>(K, Kh, Kl, NKV, totk);
    }

    // V split (no rope)
    {
        int n4 = (B * S * NKV * HD) / 4;
        split_kernel<<<(n4 + 255) / 256, 256>>>(V, Vh, Vl, n4);
    }

    // chunk means + selection
    kmean_kernel<<<B * NCH * NKV, 128>>>();
    select_kernel<<<(B * NH * S) / 8, 256>>>();

    // tensor-core sparse attention (pipelined, warp-skip)
    attn_mma_kernel<<<dim3(S / AQ, NH, B), 256, AT_SMEM_BYTES>>>();

    // output projection (3-stage pipelined)
    gemm_out_kernel<<<dim3(16, 32), 256, GEMM_SMEM>>>(out);
}